// round 1
// baseline (speedup 1.0000x reference)
#include <cuda_runtime.h>
#include <cuda_bf16.h>
#include <cstdint>

#define BATCH 4
#define NC 32
#define CIN 224
#define VOL 32768
#define KT 16512

// scratch (device globals; no allocation)
__device__ float  g_state[BATCH * NC * VOL];     // 16.8 MB
__device__ float  g_feat [BATCH * CIN * VOL];    // 117 MB
__device__ double g_sumd [BATCH * CIN];
__device__ double g_sqd  [BATCH * CIN];
__device__ float  g_zn   [BATCH];
__device__ float  g_theta[BATCH * KT];
__device__ float  g_w    [BATCH * KT];

// offsets (floats) inside per-batch g_w block
#define WC_OFF  0       // [224][64] col-major over outputs (0..31 = W_in', 32..63 = W_sh')
#define B64_OFF 14336   // 64 folded biases
#define WM_OFF  14400   // [j][i] = w_mid[i][j]
#define BM_OFF  15424
#define WO_OFF  15456   // [i][o] = w_out[o][i]
#define BO_OFF  16480

// ---------------- setup kernels ----------------

__global__ void k_norm(const float* __restrict__ z) {
    int b = blockIdx.x, t = threadIdx.x;
    float v0 = z[b * 512 + t], v1 = z[b * 512 + 256 + t];
    float s = v0 * v0 + v1 * v1;
    #pragma unroll
    for (int o = 16; o; o >>= 1) s += __shfl_down_sync(~0u, s, o);
    __shared__ float sh[8];
    if ((t & 31) == 0) sh[t >> 5] = s;
    __syncthreads();
    if (t < 8) {
        float x = sh[t];
        #pragma unroll
        for (int o = 4; o; o >>= 1) x += __shfl_down_sync(0xffu, x, o);
        if (t == 0) g_zn[b] = fmaxf(sqrtf(x), 1e-12f);
    }
}

__global__ void k_init(const float* __restrict__ z) {
    int b = blockIdx.y;
    int v = (blockIdx.x << 8) + threadIdx.x;
    float val = 0.f;
    if (v < 512) val = z[b * 512 + v] / g_zn[b];
    #pragma unroll
    for (int c = 0; c < NC; c++) g_state[((b * NC + c) << 15) + v] = val;
}

__global__ void k_theta(const int* __restrict__ y, const float* __restrict__ hw,
                        const float* __restrict__ hb) {
    int i = blockIdx.x * 256 + threadIdx.x;
    if (i >= BATCH * KT) return;
    int b = i / KT, k = i - b * KT;
    g_theta[i] = hw[y[b] * KT + k] + hb[k];
}

__global__ void k_zero() {
    int i = blockIdx.x * 256 + threadIdx.x;
    if (i < BATCH * CIN) { g_sumd[i] = 0.0; g_sqd[i] = 0.0; }
}

// ---------------- sobel + stats ----------------
// tile: 4(D) x 4(H) x 32(W full) outputs; +-2 halo in D,H; separable passes in smem

__global__ void __launch_bounds__(256) k_sobel() {
    __shared__ float sx[2048];        // [dd 8][hh 8][w 32]
    __shared__ float sA[2][2048];     // W-pass smooth / deriv
    __shared__ float sB[3][1024];     // [dd 8][hh 4][w 32]
    int b = blockIdx.z, c = blockIdx.y;
    int td = blockIdx.x >> 3, th = blockIdx.x & 7;
    int d0 = td * 4, h0 = th * 4;
    const float* xin = g_state + ((b * NC + c) << 15);
    int tid = threadIdx.x;

    for (int i = tid; i < 2048; i += 256) {
        int w = i & 31, hh = (i >> 5) & 7, dd = i >> 8;
        int gh = h0 + hh - 2, gd = d0 + dd - 2;
        float val = 0.f;
        if ((unsigned)gh < 32u && (unsigned)gd < 32u)
            val = xin[(gd << 10) + (gh << 5) + w];
        sx[i] = val;
    }
    __syncthreads();

    float psum[7], psq[7];
    #pragma unroll
    for (int g = 0; g < 7; g++) { psum[g] = 0.f; psq[g] = 0.f; }

    // ---- k = 3 : d = {-1,0,1}, s = {1,2,1} ----
    for (int i = tid; i < 2048; i += 256) {
        int w = i & 31; int rb = i & ~31;
        float x0 = (w >= 1) ? sx[rb + w - 1] : 0.f;
        float x1 = sx[i];
        float x2 = (w <= 30) ? sx[rb + w + 1] : 0.f;
        sA[0][i] = x0 + 2.f * x1 + x2;
        sA[1][i] = x2 - x0;
    }
    __syncthreads();
    for (int i = tid; i < 1024; i += 256) {
        int w = i & 31, hh = (i >> 5) & 3, dd = i >> 7;
        int r = (dd * 8 + hh + 1) * 32 + w;
        float a0 = sA[0][r], a1 = sA[0][r + 32], a2 = sA[0][r + 64];
        sB[0][i] = a0 + 2.f * a1 + a2;
        sB[1][i] = a2 - a0;
        float b0 = sA[1][r], b1 = sA[1][r + 32], b2 = sA[1][r + 64];
        sB[2][i] = b0 + 2.f * b1 + b2;
    }
    __syncthreads();
    for (int pos = tid; pos < 512; pos += 256) {
        int w = pos & 31, hh = (pos >> 5) & 3, ddo = pos >> 7;
        int r = ((ddo + 1) * 4 + hh) * 32 + w;
        float ax0 = sB[0][r + 256] - sB[0][r];
        float ax1 = sB[1][r] + 2.f * sB[1][r + 128] + sB[1][r + 256];
        float ax2 = sB[2][r] + 2.f * sB[2][r + 128] + sB[2][r + 256];
        int v = ((d0 + ddo) << 10) + ((h0 + hh) << 5) + w;
        float idv = sx[((ddo + 2) * 8 + hh + 2) * 32 + w];
        g_feat[(b * CIN + c) * VOL + v]      = idv;
        g_feat[(b * CIN + 32 + c) * VOL + v] = ax0;
        g_feat[(b * CIN + 64 + c) * VOL + v] = ax1;
        g_feat[(b * CIN + 96 + c) * VOL + v] = ax2;
        psum[0] += idv; psq[0] += idv * idv;
        psum[1] += ax0; psq[1] += ax0 * ax0;
        psum[2] += ax1; psq[2] += ax1 * ax1;
        psum[3] += ax2; psq[3] += ax2 * ax2;
    }
    __syncthreads();

    // ---- k = 5 : d = {-1,-R2,0,R2,1}, s = {1,1+R2,2,1+R2,1} ----
    const float R2 = 0.70710678118654752f;
    for (int i = tid; i < 2048; i += 256) {
        int w = i & 31; int rb = i & ~31;
        float xm2 = (w >= 2) ? sx[rb + w - 2] : 0.f;
        float xm1 = (w >= 1) ? sx[rb + w - 1] : 0.f;
        float x0  = sx[i];
        float xp1 = (w <= 30) ? sx[rb + w + 1] : 0.f;
        float xp2 = (w <= 29) ? sx[rb + w + 2] : 0.f;
        sA[0][i] = xm2 + (1.f + R2) * (xm1 + xp1) + 2.f * x0 + xp2;
        sA[1][i] = (xp2 - xm2) + R2 * (xp1 - xm1);
    }
    __syncthreads();
    for (int i = tid; i < 1024; i += 256) {
        int w = i & 31, hh = (i >> 5) & 3, dd = i >> 7;
        int r = (dd * 8 + hh) * 32 + w;
        float a0 = sA[0][r], a1 = sA[0][r + 32], a2 = sA[0][r + 64],
              a3 = sA[0][r + 96], a4 = sA[0][r + 128];
        sB[0][i] = a0 + (1.f + R2) * (a1 + a3) + 2.f * a2 + a4;
        sB[1][i] = (a4 - a0) + R2 * (a3 - a1);
        float b0 = sA[1][r], b1 = sA[1][r + 32], b2 = sA[1][r + 64],
              b3 = sA[1][r + 96], b4 = sA[1][r + 128];
        sB[2][i] = b0 + (1.f + R2) * (b1 + b3) + 2.f * b2 + b4;
    }
    __syncthreads();
    for (int pos = tid; pos < 512; pos += 256) {
        int w = pos & 31, hh = (pos >> 5) & 3, ddo = pos >> 7;
        int r = (ddo * 4 + hh) * 32 + w;
        float ax0 = (sB[0][r + 512] - sB[0][r]) + R2 * (sB[0][r + 384] - sB[0][r + 128]);
        float ax1 = sB[1][r] + (1.f + R2) * (sB[1][r + 128] + sB[1][r + 384])
                  + 2.f * sB[1][r + 256] + sB[1][r + 512];
        float ax2 = sB[2][r] + (1.f + R2) * (sB[2][r + 128] + sB[2][r + 384])
                  + 2.f * sB[2][r + 256] + sB[2][r + 512];
        int v = ((d0 + ddo) << 10) + ((h0 + hh) << 5) + w;
        g_feat[(b * CIN + 128 + c) * VOL + v] = ax0;
        g_feat[(b * CIN + 160 + c) * VOL + v] = ax1;
        g_feat[(b * CIN + 192 + c) * VOL + v] = ax2;
        psum[4] += ax0; psq[4] += ax0 * ax0;
        psum[5] += ax1; psq[5] += ax1 * ax1;
        psum[6] += ax2; psq[6] += ax2 * ax2;
    }

    int lane = tid & 31;
    #pragma unroll
    for (int g = 0; g < 7; g++) {
        float s = psum[g], q = psq[g];
        #pragma unroll
        for (int o = 16; o; o >>= 1) {
            s += __shfl_down_sync(~0u, s, o);
            q += __shfl_down_sync(~0u, q, o);
        }
        if (lane == 0) {
            atomicAdd(&g_sumd[b * CIN + g * 32 + c], (double)s);
            atomicAdd(&g_sqd [b * CIN + g * 32 + c], (double)q);
        }
    }
}

// ---------------- finalize stats + fold norm into weights ----------------

__global__ void k_fold() {
    int b = blockIdx.x, tid = threadIdx.x;
    __shared__ float smean[CIN], srs[CIN];
    if (tid < CIN) {
        double m = g_sumd[b * CIN + tid] * (1.0 / 32768.0);
        double var = g_sqd[b * CIN + tid] * (1.0 / 32768.0) - m * m;
        smean[tid] = (float)m;
        srs[tid] = (float)rsqrt(var + 1e-5);
    }
    __syncthreads();
    const float* th = g_theta + b * KT;
    float* w = g_w + b * KT;
    if (tid < 64) {
        int off = (tid < 32) ? tid * 224 : 9312 + (tid - 32) * 224;
        float corr = 0.f;
        for (int cc = 0; cc < 224; cc++) {
            float wv = th[off + cc] * srs[cc];
            w[WC_OFF + cc * 64 + tid] = wv;
            corr += wv * smean[cc];
        }
        float braw = (tid < 32) ? th[7168 + tid] : th[16480 + tid - 32];
        w[B64_OFF + tid] = braw - corr;
    }
    for (int i = tid; i < 1024; i += 256) {
        int r = i >> 5, cc = i & 31;
        w[WM_OFF + cc * 32 + r] = th[7200 + r * 32 + cc];
        w[WO_OFF + cc * 32 + r] = th[8256 + r * 32 + cc];
    }
    if (tid < 32) {
        w[BM_OFF + tid] = th[8224 + tid];
        w[BO_OFF + tid] = th[9280 + tid];
    }
}

// ---------------- fused residual MLP (packed f32x2 FMA) ----------------

__global__ void __launch_bounds__(256) k_residual() {
    extern __shared__ float sw[];
    int b = blockIdx.y;
    const float* gw = g_w + b * KT;
    for (int i = threadIdx.x; i < KT; i += 256) sw[i] = gw[i];
    __syncthreads();
    int v = (blockIdx.x << 8) + threadIdx.x;
    const float* feat = g_feat + b * CIN * VOL + v;
    unsigned swa = (unsigned)__cvta_generic_to_shared(sw);

    unsigned long long acc[32];
    #pragma unroll
    for (int p = 0; p < 32; p++)
        asm volatile("ld.shared.b64 %0, [%1];" : "=l"(acc[p])
                     : "r"(swa + (B64_OFF + 2 * p) * 4));

    #pragma unroll 2
    for (int cc = 0; cc < CIN; cc++) {
        float xc = feat[cc << 15];
        unsigned long long xx;
        asm("mov.b64 %0, {%1, %1};" : "=l"(xx) : "f"(xc));
        unsigned base = swa + cc * 256;
        #pragma unroll
        for (int p = 0; p < 16; p++) {
            unsigned long long w0, w1;
            asm volatile("ld.shared.v2.b64 {%0, %1}, [%2];"
                         : "=l"(w0), "=l"(w1) : "r"(base + p * 16));
            asm("fma.rn.f32x2 %0, %1, %2, %0;" : "+l"(acc[2 * p])     : "l"(w0), "l"(xx));
            asm("fma.rn.f32x2 %0, %1, %2, %0;" : "+l"(acc[2 * p + 1]) : "l"(w1), "l"(xx));
        }
    }

    float h[32], s[32];
    #pragma unroll
    for (int p = 0; p < 16; p++) {
        float lo, hi;
        asm("mov.b64 {%0, %1}, %2;" : "=f"(lo), "=f"(hi) : "l"(acc[p]));
        h[2 * p]     = lo > 0.f ? lo : 0.2f * lo;
        h[2 * p + 1] = hi > 0.f ? hi : 0.2f * hi;
    }
    #pragma unroll
    for (int p = 16; p < 32; p++) {
        float lo, hi;
        asm("mov.b64 {%0, %1}, %2;" : "=f"(lo), "=f"(hi) : "l"(acc[p]));
        s[2 * (p - 16)]     = lo;
        s[2 * (p - 16) + 1] = hi;
    }

    unsigned long long a2[16];
    #pragma unroll
    for (int p = 0; p < 16; p++)
        asm volatile("ld.shared.b64 %0, [%1];" : "=l"(a2[p])
                     : "r"(swa + (BM_OFF + 2 * p) * 4));
    #pragma unroll
    for (int j = 0; j < 32; j++) {
        unsigned long long xx;
        asm("mov.b64 %0, {%1, %1};" : "=l"(xx) : "f"(h[j]));
        unsigned base = swa + (WM_OFF + j * 32) * 4;
        #pragma unroll
        for (int p = 0; p < 8; p++) {
            unsigned long long w0, w1;
            asm volatile("ld.shared.v2.b64 {%0, %1}, [%2];"
                         : "=l"(w0), "=l"(w1) : "r"(base + p * 16));
            asm("fma.rn.f32x2 %0, %1, %2, %0;" : "+l"(a2[2 * p])     : "l"(w0), "l"(xx));
            asm("fma.rn.f32x2 %0, %1, %2, %0;" : "+l"(a2[2 * p + 1]) : "l"(w1), "l"(xx));
        }
    }
    float h2[32];
    #pragma unroll
    for (int p = 0; p < 16; p++) {
        float lo, hi;
        asm("mov.b64 {%0, %1}, %2;" : "=f"(lo), "=f"(hi) : "l"(a2[p]));
        h2[2 * p]     = lo > 0.f ? lo : 0.2f * lo;
        h2[2 * p + 1] = hi > 0.f ? hi : 0.2f * hi;
    }

    unsigned long long a3[16];
    #pragma unroll
    for (int p = 0; p < 16; p++)
        asm volatile("ld.shared.b64 %0, [%1];" : "=l"(a3[p])
                     : "r"(swa + (BO_OFF + 2 * p) * 4));
    #pragma unroll
    for (int i = 0; i < 32; i++) {
        unsigned long long xx;
        asm("mov.b64 %0, {%1, %1};" : "=l"(xx) : "f"(h2[i]));
        unsigned base = swa + (WO_OFF + i * 32) * 4;
        #pragma unroll
        for (int p = 0; p < 8; p++) {
            unsigned long long w0, w1;
            asm volatile("ld.shared.v2.b64 {%0, %1}, [%2];"
                         : "=l"(w0), "=l"(w1) : "r"(base + p * 16));
            asm("fma.rn.f32x2 %0, %1, %2, %0;" : "+l"(a3[2 * p])     : "l"(w0), "l"(xx));
            asm("fma.rn.f32x2 %0, %1, %2, %0;" : "+l"(a3[2 * p + 1]) : "l"(w1), "l"(xx));
        }
    }

    float* st = g_state + b * NC * VOL + v;
    #pragma unroll
    for (int p = 0; p < 16; p++) {
        float t0, t1;
        asm("mov.b64 {%0, %1}, %2;" : "=f"(t0), "=f"(t1) : "l"(a3[p]));
        int o0 = 2 * p, o1 = 2 * p + 1;
        st[o0 << 15] = st[o0 << 15] + 0.1f * (t0 + s[o0]);
        st[o1 << 15] = st[o1 << 15] + 0.1f * (t1 + s[o1]);
    }
}

// ---------------- channel mean ----------------

__global__ void k_final(float* __restrict__ out) {
    int b = blockIdx.y;
    int v = (blockIdx.x << 8) + threadIdx.x;
    const float* st = g_state + b * NC * VOL + v;
    float s = 0.f;
    #pragma unroll
    for (int c = 0; c < NC; c++) s += st[c << 15];
    out[b * VOL + v] = s * (1.f / 32.f);
}

// ---------------- launch ----------------

extern "C" void kernel_launch(void* const* d_in, const int* in_sizes, int n_in,
                              void* d_out, int out_size) {
    const float* z  = (const float*)d_in[0];
    const int*   y  = (const int*)d_in[1];
    const float* hw = (const float*)d_in[2];
    const float* hb = (const float*)d_in[3];
    float* out = (float*)d_out;
    (void)in_sizes; (void)n_in; (void)out_size;

    cudaFuncSetAttribute(k_residual, cudaFuncAttributeMaxDynamicSharedMemorySize, KT * 4);

    k_norm<<<4, 256>>>(z);
    k_init<<<dim3(128, 4), 256>>>(z);
    k_theta<<<(BATCH * KT + 255) / 256, 256>>>(y, hw, hb);

    for (int it = 0; it < 4; it++) {
        k_zero<<<4, 256>>>();
        k_sobel<<<dim3(64, 32, 4), 256>>>();
        k_fold<<<4, 256>>>();
        k_residual<<<dim3(128, 4), 256, KT * 4>>>();
    }
    k_final<<<dim3(128, 4), 256>>>(out);
}

// round 2
// speedup vs baseline: 1.8255x; 1.8255x over previous
#include <cuda_runtime.h>
#include <cuda_bf16.h>
#include <cstdint>

#define BATCH 4
#define NC 32
#define CIN 224
#define VOL 32768
#define KT 16512

__device__ float  g_state[BATCH * NC * VOL];     // 16.8 MB
__device__ float  g_feat [BATCH * CIN * VOL];    // 117 MB (identity block unused)
__device__ double g_sumd [BATCH * CIN];
__device__ double g_sqd  [BATCH * CIN];
__device__ float  g_zn   [BATCH];
__device__ float  g_theta[BATCH * KT];
__device__ float  g_w    [BATCH * KT];

// offsets (floats) inside per-batch g_w block
#define WC_OFF  0       // [224][64] row per channel: 0..31 = W_in', 32..63 = W_sh'
#define B64_OFF 14336
#define WM_OFF  14400   // wm[j*32+i] = w_mid[i][j]
#define BM_OFF  15424
#define WO_OFF  15456   // wo[i*32+o] = w_out[o][i]
#define BO_OFF  16480

#define FMA2(acc, w, x) asm("fma.rn.f32x2 %0, %1, %2, %0;" : "+l"(acc) : "l"(w), "l"(x))
#define BCAST(d, f)     asm("mov.b64 %0, {%1, %1};" : "=l"(d) : "f"(f))
#define UNPK(lo, hi, q) asm("mov.b64 {%0, %1}, %2;" : "=f"(lo), "=f"(hi) : "l"(q))
#define CPA16(dst, src) asm volatile("cp.async.cg.shared.global [%0], [%1], 16;" :: "r"(dst), "l"(src))
#define CPCOMMIT()      asm volatile("cp.async.commit_group;")
#define CPWAIT(n)       asm volatile("cp.async.wait_group %0;" :: "n"(n))

// ---------------- setup ----------------

__global__ void k_norm(const float* __restrict__ z) {
    int b = blockIdx.x, t = threadIdx.x;
    float v0 = z[b * 512 + t], v1 = z[b * 512 + 256 + t];
    float s = v0 * v0 + v1 * v1;
    #pragma unroll
    for (int o = 16; o; o >>= 1) s += __shfl_down_sync(~0u, s, o);
    __shared__ float sh[8];
    if ((t & 31) == 0) sh[t >> 5] = s;
    __syncthreads();
    if (t < 8) {
        float x = sh[t];
        #pragma unroll
        for (int o = 4; o; o >>= 1) x += __shfl_down_sync(0xffu, x, o);
        if (t == 0) g_zn[b] = fmaxf(sqrtf(x), 1e-12f);
    }
}

__global__ void k_init(const float* __restrict__ z) {
    int b = blockIdx.y;
    int v = (blockIdx.x << 8) + threadIdx.x;
    float val = 0.f;
    if (v < 512) val = z[b * 512 + v] / g_zn[b];
    #pragma unroll
    for (int c = 0; c < NC; c++) g_state[((b * NC + c) << 15) + v] = val;
}

__global__ void k_theta(const int* __restrict__ y, const float* __restrict__ hw,
                        const float* __restrict__ hb) {
    int i = blockIdx.x * 256 + threadIdx.x;
    if (i >= BATCH * KT) return;
    int b = i / KT, k = i - b * KT;
    g_theta[i] = hw[y[b] * KT + k] + hb[k];
}

// ---------------- sobel + stats ----------------

__global__ void __launch_bounds__(256) k_sobel() {
    __shared__ float sx[2048];
    __shared__ float sA[2][2048];
    __shared__ float sB[3][1024];
    int b = blockIdx.z, c = blockIdx.y;
    int td = blockIdx.x >> 3, th = blockIdx.x & 7;
    int d0 = td * 4, h0 = th * 4;
    const float* xin = g_state + ((b * NC + c) << 15);
    int tid = threadIdx.x;

    for (int i = tid; i < 2048; i += 256) {
        int w = i & 31, hh = (i >> 5) & 7, dd = i >> 8;
        int gh = h0 + hh - 2, gd = d0 + dd - 2;
        float val = 0.f;
        if ((unsigned)gh < 32u && (unsigned)gd < 32u)
            val = xin[(gd << 10) + (gh << 5) + w];
        sx[i] = val;
    }
    __syncthreads();

    float psum[7], psq[7];
    #pragma unroll
    for (int g = 0; g < 7; g++) { psum[g] = 0.f; psq[g] = 0.f; }

    // ---- k=3 ----
    for (int i = tid; i < 2048; i += 256) {
        int w = i & 31; int rb = i & ~31;
        float x0 = (w >= 1) ? sx[rb + w - 1] : 0.f;
        float x1 = sx[i];
        float x2 = (w <= 30) ? sx[rb + w + 1] : 0.f;
        sA[0][i] = x0 + 2.f * x1 + x2;
        sA[1][i] = x2 - x0;
    }
    __syncthreads();
    for (int i = tid; i < 1024; i += 256) {
        int w = i & 31, hh = (i >> 5) & 3, dd = i >> 7;
        int r = (dd * 8 + hh + 1) * 32 + w;
        float a0 = sA[0][r], a1 = sA[0][r + 32], a2 = sA[0][r + 64];
        sB[0][i] = a0 + 2.f * a1 + a2;
        sB[1][i] = a2 - a0;
        float b0 = sA[1][r], b1 = sA[1][r + 32], b2 = sA[1][r + 64];
        sB[2][i] = b0 + 2.f * b1 + b2;
    }
    __syncthreads();
    for (int pos = tid; pos < 512; pos += 256) {
        int w = pos & 31, hh = (pos >> 5) & 3, ddo = pos >> 7;
        int r = ((ddo + 1) * 4 + hh) * 32 + w;
        float ax0 = sB[0][r + 256] - sB[0][r];
        float ax1 = sB[1][r] + 2.f * sB[1][r + 128] + sB[1][r + 256];
        float ax2 = sB[2][r] + 2.f * sB[2][r + 128] + sB[2][r + 256];
        int v = ((d0 + ddo) << 10) + ((h0 + hh) << 5) + w;
        float idv = sx[((ddo + 2) * 8 + hh + 2) * 32 + w];
        g_feat[(b * CIN + 32 + c) * VOL + v] = ax0;
        g_feat[(b * CIN + 64 + c) * VOL + v] = ax1;
        g_feat[(b * CIN + 96 + c) * VOL + v] = ax2;
        psum[0] += idv; psq[0] += idv * idv;
        psum[1] += ax0; psq[1] += ax0 * ax0;
        psum[2] += ax1; psq[2] += ax1 * ax1;
        psum[3] += ax2; psq[3] += ax2 * ax2;
    }
    __syncthreads();

    // ---- k=5 ----
    const float R2 = 0.70710678118654752f;
    for (int i = tid; i < 2048; i += 256) {
        int w = i & 31; int rb = i & ~31;
        float xm2 = (w >= 2) ? sx[rb + w - 2] : 0.f;
        float xm1 = (w >= 1) ? sx[rb + w - 1] : 0.f;
        float x0  = sx[i];
        float xp1 = (w <= 30) ? sx[rb + w + 1] : 0.f;
        float xp2 = (w <= 29) ? sx[rb + w + 2] : 0.f;
        sA[0][i] = xm2 + (1.f + R2) * (xm1 + xp1) + 2.f * x0 + xp2;
        sA[1][i] = (xp2 - xm2) + R2 * (xp1 - xm1);
    }
    __syncthreads();
    for (int i = tid; i < 1024; i += 256) {
        int w = i & 31, hh = (i >> 5) & 3, dd = i >> 7;
        int r = (dd * 8 + hh) * 32 + w;
        float a0 = sA[0][r], a1 = sA[0][r + 32], a2 = sA[0][r + 64],
              a3 = sA[0][r + 96], a4 = sA[0][r + 128];
        sB[0][i] = a0 + (1.f + R2) * (a1 + a3) + 2.f * a2 + a4;
        sB[1][i] = (a4 - a0) + R2 * (a3 - a1);
        float b0 = sA[1][r], b1 = sA[1][r + 32], b2 = sA[1][r + 64],
              b3 = sA[1][r + 96], b4 = sA[1][r + 128];
        sB[2][i] = b0 + (1.f + R2) * (b1 + b3) + 2.f * b2 + b4;
    }
    __syncthreads();
    for (int pos = tid; pos < 512; pos += 256) {
        int w = pos & 31, hh = (pos >> 5) & 3, ddo = pos >> 7;
        int r = (ddo * 4 + hh) * 32 + w;
        float ax0 = (sB[0][r + 512] - sB[0][r]) + R2 * (sB[0][r + 384] - sB[0][r + 128]);
        float ax1 = sB[1][r] + (1.f + R2) * (sB[1][r + 128] + sB[1][r + 384])
                  + 2.f * sB[1][r + 256] + sB[1][r + 512];
        float ax2 = sB[2][r] + (1.f + R2) * (sB[2][r + 128] + sB[2][r + 384])
                  + 2.f * sB[2][r + 256] + sB[2][r + 512];
        int v = ((d0 + ddo) << 10) + ((h0 + hh) << 5) + w;
        g_feat[(b * CIN + 128 + c) * VOL + v] = ax0;
        g_feat[(b * CIN + 160 + c) * VOL + v] = ax1;
        g_feat[(b * CIN + 192 + c) * VOL + v] = ax2;
        psum[4] += ax0; psq[4] += ax0 * ax0;
        psum[5] += ax1; psq[5] += ax1 * ax1;
        psum[6] += ax2; psq[6] += ax2 * ax2;
    }

    int lane = tid & 31;
    #pragma unroll
    for (int g = 0; g < 7; g++) {
        float s = psum[g], q = psq[g];
        #pragma unroll
        for (int o = 16; o; o >>= 1) {
            s += __shfl_down_sync(~0u, s, o);
            q += __shfl_down_sync(~0u, q, o);
        }
        if (lane == 0) {
            atomicAdd(&g_sumd[b * CIN + g * 32 + c], (double)s);
            atomicAdd(&g_sqd [b * CIN + g * 32 + c], (double)q);
        }
    }
}

// ---------------- fold norm into weights (+ zero stats for next iter) ----------------

__global__ void k_fold() {
    int b = blockIdx.x, tid = threadIdx.x;
    __shared__ float smean[CIN], srs[CIN];
    if (tid < CIN) {
        double m = g_sumd[b * CIN + tid] * (1.0 / 32768.0);
        double var = g_sqd[b * CIN + tid] * (1.0 / 32768.0) - m * m;
        smean[tid] = (float)m;
        srs[tid] = (float)rsqrt(var + 1e-5);
    }
    __syncthreads();
    const float* th = g_theta + b * KT;
    float* w = g_w + b * KT;
    if (tid < 64) {
        int off = (tid < 32) ? tid * 224 : 9312 + (tid - 32) * 224;
        float corr = 0.f;
        for (int cc = 0; cc < 224; cc++) {
            float wv = th[off + cc] * srs[cc];
            w[WC_OFF + cc * 64 + tid] = wv;
            corr += wv * smean[cc];
        }
        float braw = (tid < 32) ? th[7168 + tid] : th[16480 + tid - 32];
        w[B64_OFF + tid] = braw - corr;
    }
    for (int i = tid; i < 1024; i += 256) {
        int r = i >> 5, cc = i & 31;
        w[WM_OFF + cc * 32 + r] = th[7200 + r * 32 + cc];
        w[WO_OFF + cc * 32 + r] = th[8256 + r * 32 + cc];
    }
    if (tid < 32) {
        w[BM_OFF + tid] = th[8224 + tid];
        w[BO_OFF + tid] = th[9280 + tid];
    }
    __syncthreads();
    if (tid < CIN) { g_sumd[b * CIN + tid] = 0.0; g_sqd[b * CIN + tid] = 0.0; }
}

// ---------------- register-blocked residual MLP ----------------
// block: 64 outputs x 128 voxels, 256 threads; thread = 8 out x 4 vox micro-tile

// shared layout (floats)
#define XS   0       // [2][8][128]
#define WS   2048    // [2][8][64]
#define HSO  3072    // [64][132]
#define H2S  11520   // [32][132]
#define SWB  15744   // b64[64] | bm[32] | bo[32] | wm[1024] | wo[1024]
#define SM_FLOATS 17920

__global__ void __launch_bounds__(256) k_residual() {
    extern __shared__ float sm[];
    const int tid = threadIdx.x;
    const int wid = tid >> 5, lane = tid & 31;
    const int b = blockIdx.y;
    const int v0 = blockIdx.x << 7;
    const float* gw = g_w + b * KT;
    unsigned swa = (unsigned)__cvta_generic_to_shared(sm);

    // small weights -> smem
    if (tid < 64)  sm[SWB + tid]       = gw[B64_OFF + tid];
    if (tid < 32)  sm[SWB + 64 + tid]  = gw[BM_OFF + tid];
    if (tid >= 32 && tid < 64) sm[SWB + 96 + (tid - 32)] = gw[BO_OFF + tid - 32];
    for (int i = tid; i < 1024; i += 256) sm[SWB + 128 + i]  = gw[WM_OFF + i];
    for (int i = tid; i < 1024; i += 256) sm[SWB + 1152 + i] = gw[WO_OFF + i];

    // chunk copy: 8 channels of X (8x128) + W (8x64)
    const int ckk = tid >> 5, clw = tid & 31;
    auto issue = [&](int ch, int buf) {
        int cc = ch * 8 + ckk;
        const float* xsrc = (cc < 32)
            ? g_state + ((size_t)(b * NC + cc) << 15) + v0 + clw * 4
            : g_feat  + ((size_t)(b * CIN + cc) << 15) + v0 + clw * 4;
        CPA16(swa + (XS + buf * 1024 + ckk * 128 + clw * 4) * 4, xsrc);
        if (tid < 128) {
            const float* wsrc = gw + WC_OFF + ch * 512 + tid * 4;
            CPA16(swa + (WS + buf * 512 + tid * 4) * 4, wsrc);
        }
    };

    issue(0, 0); CPCOMMIT();
    __syncthreads();   // small weights visible

    unsigned long long acc[16];
    {
        const unsigned long long* bp =
            reinterpret_cast<const unsigned long long*>(sm + SWB + wid * 8);
        #pragma unroll
        for (int j = 0; j < 4; j++) {
            unsigned long long bj = bp[j];
            acc[j * 4 + 0] = bj; acc[j * 4 + 1] = bj;
            acc[j * 4 + 2] = bj; acc[j * 4 + 3] = bj;
        }
    }

    for (int ch = 0; ch < 28; ch++) {
        if (ch < 27) { issue(ch + 1, (ch + 1) & 1); CPCOMMIT(); CPWAIT(1); }
        else         { CPWAIT(0); }
        __syncthreads();
        const float* xb = sm + XS + (ch & 1) * 1024;
        const float* wb = sm + WS + (ch & 1) * 512;
        #pragma unroll
        for (int kk = 0; kk < 8; kk++) {
            float4 xv = *reinterpret_cast<const float4*>(xb + kk * 128 + lane * 4);
            unsigned long long xq0, xq1, xq2, xq3;
            BCAST(xq0, xv.x); BCAST(xq1, xv.y); BCAST(xq2, xv.z); BCAST(xq3, xv.w);
            const ulonglong2* wp =
                reinterpret_cast<const ulonglong2*>(wb + kk * 64 + wid * 8);
            ulonglong2 wA = wp[0], wB = wp[1];
            FMA2(acc[0],  wA.x, xq0); FMA2(acc[1],  wA.x, xq1);
            FMA2(acc[2],  wA.x, xq2); FMA2(acc[3],  wA.x, xq3);
            FMA2(acc[4],  wA.y, xq0); FMA2(acc[5],  wA.y, xq1);
            FMA2(acc[6],  wA.y, xq2); FMA2(acc[7],  wA.y, xq3);
            FMA2(acc[8],  wB.x, xq0); FMA2(acc[9],  wB.x, xq1);
            FMA2(acc[10], wB.x, xq2); FMA2(acc[11], wB.x, xq3);
            FMA2(acc[12], wB.y, xq0); FMA2(acc[13], wB.y, xq1);
            FMA2(acc[14], wB.y, xq2); FMA2(acc[15], wB.y, xq3);
        }
        __syncthreads();
    }

    // stage-1 epilogue: accs -> hs[64][132]
    #pragma unroll
    for (int j = 0; j < 4; j++) {
        float lo0, hi0, lo1, hi1, lo2, hi2, lo3, hi3;
        UNPK(lo0, hi0, acc[j * 4 + 0]); UNPK(lo1, hi1, acc[j * 4 + 1]);
        UNPK(lo2, hi2, acc[j * 4 + 2]); UNPK(lo3, hi3, acc[j * 4 + 3]);
        int o = wid * 8 + 2 * j;
        *reinterpret_cast<float4*>(sm + HSO + o * 132 + lane * 4)
            = make_float4(lo0, lo1, lo2, lo3);
        *reinterpret_cast<float4*>(sm + HSO + (o + 1) * 132 + lane * 4)
            = make_float4(hi0, hi1, hi2, hi3);
    }
    __syncthreads();

    // stage 2: per voxel, split over two halves of the block
    const int v = tid & 127, half = tid >> 7;
    const int obase = half * 16;

    float hv[32];
    #pragma unroll
    for (int j = 0; j < 32; j++) {
        float t = sm[HSO + j * 132 + v];
        hv[j] = t > 0.f ? t : 0.2f * t;
    }

    unsigned long long m[8];
    {
        const unsigned long long* bmp =
            reinterpret_cast<const unsigned long long*>(sm + SWB + 64 + obase);
        #pragma unroll
        for (int p = 0; p < 8; p++) m[p] = bmp[p];
    }
    #pragma unroll
    for (int j = 0; j < 32; j++) {
        unsigned long long xj; BCAST(xj, hv[j]);
        const unsigned long long* wr =
            reinterpret_cast<const unsigned long long*>(sm + SWB + 128 + j * 32 + obase);
        #pragma unroll
        for (int p = 0; p < 8; p++) FMA2(m[p], wr[p], xj);
    }
    #pragma unroll
    for (int p = 0; p < 8; p++) {
        float lo, hi; UNPK(lo, hi, m[p]);
        lo = lo > 0.f ? lo : 0.2f * lo;
        hi = hi > 0.f ? hi : 0.2f * hi;
        sm[H2S + (obase + 2 * p) * 132 + v]     = lo;
        sm[H2S + (obase + 2 * p + 1) * 132 + v] = hi;
    }
    __syncthreads();

    unsigned long long f[8];
    {
        const unsigned long long* bop =
            reinterpret_cast<const unsigned long long*>(sm + SWB + 96 + obase);
        #pragma unroll
        for (int p = 0; p < 8; p++) f[p] = bop[p];
    }
    #pragma unroll
    for (int i = 0; i < 32; i++) {
        float h2 = sm[H2S + i * 132 + v];
        unsigned long long xi; BCAST(xi, h2);
        const unsigned long long* wr =
            reinterpret_cast<const unsigned long long*>(sm + SWB + 1152 + i * 32 + obase);
        #pragma unroll
        for (int p = 0; p < 8; p++) FMA2(f[p], wr[p], xi);
    }

    float* st = g_state + ((size_t)(b * NC) << 15) + v0 + v;
    #pragma unroll
    for (int p = 0; p < 8; p++) {
        float t0, t1; UNPK(t0, t1, f[p]);
        int o = obase + 2 * p;
        float s0 = sm[HSO + (32 + o) * 132 + v];
        float s1 = sm[HSO + (33 + o) * 132 + v];
        st[(size_t)o << 15]       += 0.1f * (t0 + s0);
        st[(size_t)(o + 1) << 15] += 0.1f * (t1 + s1);
    }
}

// ---------------- channel mean ----------------

__global__ void k_final(float* __restrict__ out) {
    int b = blockIdx.y;
    int v = (blockIdx.x << 8) + threadIdx.x;
    const float* st = g_state + b * NC * VOL + v;
    float s = 0.f;
    #pragma unroll
    for (int c = 0; c < NC; c++) s += st[c << 15];
    out[b * VOL + v] = s * (1.f / 32.f);
}

// ---------------- launch ----------------

extern "C" void kernel_launch(void* const* d_in, const int* in_sizes, int n_in,
                              void* d_out, int out_size) {
    const float* z  = (const float*)d_in[0];
    const int*   y  = (const int*)d_in[1];
    const float* hw = (const float*)d_in[2];
    const float* hb = (const float*)d_in[3];
    float* out = (float*)d_out;
    (void)in_sizes; (void)n_in; (void)out_size;

    cudaFuncSetAttribute(k_residual, cudaFuncAttributeMaxDynamicSharedMemorySize,
                         SM_FLOATS * 4);

    k_norm<<<4, 256>>>(z);
    k_init<<<dim3(128, 4), 256>>>(z);
    k_theta<<<(BATCH * KT + 255) / 256, 256>>>(y, hw, hb);

    for (int it = 0; it < 4; it++) {
        k_sobel<<<dim3(64, 32, 4), 256>>>();
        k_fold<<<4, 256>>>();
        k_residual<<<dim3(256, 4), 256, SM_FLOATS * 4>>>();
    }
    k_final<<<dim3(128, 4), 256>>>(out);
}

// round 3
// speedup vs baseline: 2.5130x; 1.3767x over previous
#include <cuda_runtime.h>
#include <cuda_bf16.h>
#include <cstdint>

#define BATCH 4
#define NC 32
#define CIN 224
#define VOL 32768
#define KT 16512

__device__ float  g_state[BATCH * NC * VOL];     // 16.8 MB
__device__ float  g_feat [BATCH * CIN * VOL];    // 117 MB (identity block unused)
__device__ double g_sumd [BATCH * CIN];
__device__ double g_sqd  [BATCH * CIN];
__device__ float  g_zn   [BATCH];
__device__ float  g_theta[BATCH * KT];
__device__ float  g_w    [BATCH * KT];

// offsets (floats) inside per-batch g_w block
#define WC_OFF  0       // [224][64] row per channel: 0..31 = W_in', 32..63 = W_sh'
#define B64_OFF 14336
#define WM_OFF  14400   // wm[j*32+i] = w_mid[i][j]
#define BM_OFF  15424
#define WO_OFF  15456   // wo[i*32+o] = w_out[o][i]
#define BO_OFF  16480

#define FMA2(acc, w, x) asm("fma.rn.f32x2 %0, %1, %2, %0;" : "+l"(acc) : "l"(w), "l"(x))
#define BCAST(d, f)     asm("mov.b64 %0, {%1, %1};" : "=l"(d) : "f"(f))
#define UNPK(lo, hi, q) asm("mov.b64 {%0, %1}, %2;" : "=f"(lo), "=f"(hi) : "l"(q))
#define CPA16(dst, src) asm volatile("cp.async.cg.shared.global [%0], [%1], 16;" :: "r"(dst), "l"(src))
#define CPCOMMIT()      asm volatile("cp.async.commit_group;")
#define CPWAIT(n)       asm volatile("cp.async.wait_group %0;" :: "n"(n))

// ---------------- setup ----------------

__global__ void k_norm(const float* __restrict__ z) {
    int b = blockIdx.x, t = threadIdx.x;
    float v0 = z[b * 512 + t], v1 = z[b * 512 + 256 + t];
    float s = v0 * v0 + v1 * v1;
    #pragma unroll
    for (int o = 16; o; o >>= 1) s += __shfl_down_sync(~0u, s, o);
    __shared__ float sh[8];
    if ((t & 31) == 0) sh[t >> 5] = s;
    __syncthreads();
    if (t < 8) {
        float x = sh[t];
        #pragma unroll
        for (int o = 4; o; o >>= 1) x += __shfl_down_sync(0xffu, x, o);
        if (t == 0) g_zn[b] = fmaxf(sqrtf(x), 1e-12f);
    }
}

__global__ void k_init(const float* __restrict__ z) {
    int b = blockIdx.y;
    int v = (blockIdx.x << 8) + threadIdx.x;
    float val = 0.f;
    if (v < 512) val = z[b * 512 + v] / g_zn[b];
    #pragma unroll
    for (int c = 0; c < NC; c++) g_state[((b * NC + c) << 15) + v] = val;
}

__global__ void k_theta(const int* __restrict__ y, const float* __restrict__ hw,
                        const float* __restrict__ hb) {
    int i = blockIdx.x * 256 + threadIdx.x;
    if (i >= BATCH * KT) return;
    int b = i / KT, k = i - b * KT;
    g_theta[i] = hw[y[b] * KT + k] + hb[k];
}

// ---------------- sobel: shfl W-pass, smem H-pass, register-window D-pass ----
// one block per (b,c); 512 threads = 16 warps; lane = w; thread owns 2 h-rows.

__global__ void __launch_bounds__(512) k_sobel() {
    __shared__ float sl[2][4][36][32];   // [buf][arr][h+2][w]
    __shared__ float red[16][14];
    const int c = blockIdx.x, b = blockIdx.y;
    const int tid = threadIdx.x;
    const int lane = tid & 31, wid = tid >> 5;
    const int h0 = wid * 2;
    const float* __restrict__ xin = g_state + ((size_t)(b * NC + c) << 15);
    float* __restrict__ featb = g_feat + (size_t)(b * CIN + c) * VOL;

    // zero the h pad rows (0,1,34,35) once
    for (int i = tid; i < 1024; i += 512) {
        int w = i & 31, r = (i >> 5) & 3, arr = (i >> 7) & 3, bu = i >> 9;
        int hp = (r < 2) ? r : r + 32;
        sl[bu][arr][hp][w] = 0.f;
    }

    const float R2 = 0.70710678118654752f;
    const float S1 = 1.f + R2;

    float stat[14];
    #pragma unroll
    for (int i = 0; i < 14; i++) stat[i] = 0.f;
    float W[2][6][5];
    #pragma unroll
    for (int r = 0; r < 2; r++)
        #pragma unroll
        for (int a = 0; a < 6; a++)
            #pragma unroll
            for (int k = 0; k < 5; k++) W[r][a][k] = 0.f;

    __syncthreads();

    float sw3[2], dw3[2], sw5[2], dw5[2];

    #pragma unroll 2
    for (int s = 0; s < 34; s++) {
        const int bu = s & 1;
        if (s < 32) {
            #pragma unroll
            for (int r = 0; r < 2; r++) {
                float xv = xin[(s << 10) + ((h0 + r) << 5) + lane];
                stat[0] += xv; stat[1] += xv * xv;
                float xm1 = __shfl_up_sync(~0u, xv, 1);   if (lane == 0)  xm1 = 0.f;
                float xm2 = __shfl_up_sync(~0u, xv, 2);   if (lane < 2)   xm2 = 0.f;
                float xp1 = __shfl_down_sync(~0u, xv, 1); if (lane == 31) xp1 = 0.f;
                float xp2 = __shfl_down_sync(~0u, xv, 2); if (lane > 29)  xp2 = 0.f;
                sw3[r] = xm1 + 2.f * xv + xp1;
                dw3[r] = xp1 - xm1;
                sw5[r] = xm2 + xp2 + S1 * (xm1 + xp1) + 2.f * xv;
                dw5[r] = (xp2 - xm2) + R2 * (xp1 - xm1);
                int hp = h0 + r + 2;
                sl[bu][0][hp][lane] = sw3[r];
                sl[bu][1][hp][lane] = dw3[r];
                sl[bu][2][hp][lane] = sw5[r];
                sl[bu][3][hp][lane] = dw5[r];
            }
        }
        __syncthreads();
        #pragma unroll
        for (int r = 0; r < 2; r++) {
            float a30, a31, a32, a50, a51, a52;
            if (s < 32) {
                int hp = h0 + r + 2;
                float s3m = sl[bu][0][hp - 1][lane], s3p = sl[bu][0][hp + 1][lane];
                float d3m = sl[bu][1][hp - 1][lane], d3p = sl[bu][1][hp + 1][lane];
                float s5m2 = sl[bu][2][hp - 2][lane], s5m1 = sl[bu][2][hp - 1][lane];
                float s5p1 = sl[bu][2][hp + 1][lane], s5p2 = sl[bu][2][hp + 2][lane];
                float d5m2 = sl[bu][3][hp - 2][lane], d5m1 = sl[bu][3][hp - 1][lane];
                float d5p1 = sl[bu][3][hp + 1][lane], d5p2 = sl[bu][3][hp + 2][lane];
                a30 = d3m + 2.f * dw3[r] + d3p;                 // S3_h(dW3) -> D_w
                a31 = s3p - s3m;                                // D3_h(sW3) -> D_h
                a32 = s3m + 2.f * sw3[r] + s3p;                 // S3_h(sW3) -> D_d later
                a50 = d5m2 + d5p2 + S1 * (d5m1 + d5p1) + 2.f * dw5[r];
                a51 = (s5p2 - s5m2) + R2 * (s5p1 - s5m1);
                a52 = s5m2 + s5p2 + S1 * (s5m1 + s5p1) + 2.f * sw5[r];
            } else {
                a30 = a31 = a32 = a50 = a51 = a52 = 0.f;
            }
            #pragma unroll
            for (int a = 0; a < 6; a++) {
                W[r][a][0] = W[r][a][1]; W[r][a][1] = W[r][a][2];
                W[r][a][2] = W[r][a][3]; W[r][a][3] = W[r][a][4];
            }
            W[r][0][4] = a32; W[r][1][4] = a31; W[r][2][4] = a30;
            W[r][3][4] = a52; W[r][4][4] = a51; W[r][5][4] = a50;

            if (s >= 2) {
                int dc = s - 2;
                // window after push holds slices [s-4..s]; dc at index 2
                float o1 = W[r][0][3] - W[r][0][1];                               // ch 32 : D_d k3
                float o2 = W[r][1][1] + 2.f * W[r][1][2] + W[r][1][3];            // ch 64 : D_h k3
                float o3 = W[r][2][1] + 2.f * W[r][2][2] + W[r][2][3];            // ch 96 : D_w k3
                float o4 = (W[r][3][4] - W[r][3][0]) + R2 * (W[r][3][3] - W[r][3][1]); // ch128
                float o5 = W[r][4][0] + W[r][4][4] + S1 * (W[r][4][1] + W[r][4][3]) + 2.f * W[r][4][2]; // ch160
                float o6 = W[r][5][0] + W[r][5][4] + S1 * (W[r][5][1] + W[r][5][3]) + 2.f * W[r][5][2]; // ch192
                int v = (dc << 10) + ((h0 + r) << 5) + lane;
                featb[(size_t)32 * VOL + v]  = o1;
                featb[(size_t)64 * VOL + v]  = o2;
                featb[(size_t)96 * VOL + v]  = o3;
                featb[(size_t)128 * VOL + v] = o4;
                featb[(size_t)160 * VOL + v] = o5;
                featb[(size_t)192 * VOL + v] = o6;
                stat[2]  += o1; stat[3]  += o1 * o1;
                stat[4]  += o2; stat[5]  += o2 * o2;
                stat[6]  += o3; stat[7]  += o3 * o3;
                stat[8]  += o4; stat[9]  += o4 * o4;
                stat[10] += o5; stat[11] += o5 * o5;
                stat[12] += o6; stat[13] += o6 * o6;
            }
        }
    }

    // block-wide stat reduction; one block owns (b,c) -> direct store, no atomics
    #pragma unroll
    for (int i = 0; i < 14; i++) {
        float v = stat[i];
        #pragma unroll
        for (int o = 16; o; o >>= 1) v += __shfl_down_sync(~0u, v, o);
        stat[i] = v;
    }
    if (lane == 0)
        #pragma unroll
        for (int i = 0; i < 14; i++) red[wid][i] = stat[i];
    __syncthreads();
    if (tid < 14) {
        double acc = 0.0;
        #pragma unroll
        for (int k = 0; k < 16; k++) acc += (double)red[k][tid];
        int g = tid >> 1;
        if (tid & 1) g_sqd [b * CIN + g * 32 + c] = acc;
        else         g_sumd[b * CIN + g * 32 + c] = acc;
    }
}

// ---------------- fold norm into weights ----------------

__global__ void k_fold() {
    int b = blockIdx.x, tid = threadIdx.x;
    __shared__ float smean[CIN], srs[CIN];
    if (tid < CIN) {
        double m = g_sumd[b * CIN + tid] * (1.0 / 32768.0);
        double var = g_sqd[b * CIN + tid] * (1.0 / 32768.0) - m * m;
        smean[tid] = (float)m;
        srs[tid] = (float)rsqrt(var + 1e-5);
    }
    __syncthreads();
    const float* th = g_theta + b * KT;
    float* w = g_w + b * KT;
    if (tid < 64) {
        int off = (tid < 32) ? tid * 224 : 9312 + (tid - 32) * 224;
        float corr = 0.f;
        for (int cc = 0; cc < 224; cc++) {
            float wv = th[off + cc] * srs[cc];
            w[WC_OFF + cc * 64 + tid] = wv;
            corr += wv * smean[cc];
        }
        float braw = (tid < 32) ? th[7168 + tid] : th[16480 + tid - 32];
        w[B64_OFF + tid] = braw - corr;
    }
    for (int i = tid; i < 1024; i += 256) {
        int r = i >> 5, cc = i & 31;
        w[WM_OFF + cc * 32 + r] = th[7200 + r * 32 + cc];
        w[WO_OFF + cc * 32 + r] = th[8256 + r * 32 + cc];
    }
    if (tid < 32) {
        w[BM_OFF + tid] = th[8224 + tid];
        w[BO_OFF + tid] = th[9280 + tid];
    }
}

// ---------------- register-blocked residual MLP ----------------
// block: 64 outputs x 128 voxels, 256 threads; thread = 8 out x 4 vox micro-tile

#define XS   0       // [2][8][128]
#define WS   2048    // [2][8][64]
#define HSO  3072    // [64][132]
#define H2S  11520   // [32][132]
#define SWB  15744   // b64[64] | bm[32] | bo[32] | wm[1024] | wo[1024]
#define SM_FLOATS 17920

__global__ void __launch_bounds__(256) k_residual() {
    extern __shared__ float sm[];
    const int tid = threadIdx.x;
    const int wid = tid >> 5, lane = tid & 31;
    const int b = blockIdx.y;
    const int v0 = blockIdx.x << 7;
    const float* gw = g_w + b * KT;
    unsigned swa = (unsigned)__cvta_generic_to_shared(sm);

    if (tid < 64)  sm[SWB + tid]       = gw[B64_OFF + tid];
    if (tid < 32)  sm[SWB + 64 + tid]  = gw[BM_OFF + tid];
    if (tid >= 32 && tid < 64) sm[SWB + 96 + (tid - 32)] = gw[BO_OFF + tid - 32];
    for (int i = tid; i < 1024; i += 256) sm[SWB + 128 + i]  = gw[WM_OFF + i];
    for (int i = tid; i < 1024; i += 256) sm[SWB + 1152 + i] = gw[WO_OFF + i];

    const int ckk = tid >> 5, clw = tid & 31;
    auto issue = [&](int ch, int buf) {
        int cc = ch * 8 + ckk;
        const float* xsrc = (cc < 32)
            ? g_state + ((size_t)(b * NC + cc) << 15) + v0 + clw * 4
            : g_feat  + ((size_t)(b * CIN + cc) << 15) + v0 + clw * 4;
        CPA16(swa + (XS + buf * 1024 + ckk * 128 + clw * 4) * 4, xsrc);
        if (tid < 128) {
            const float* wsrc = gw + WC_OFF + ch * 512 + tid * 4;
            CPA16(swa + (WS + buf * 512 + tid * 4) * 4, wsrc);
        }
    };

    issue(0, 0); CPCOMMIT();
    __syncthreads();

    unsigned long long acc[16];
    {
        const unsigned long long* bp =
            reinterpret_cast<const unsigned long long*>(sm + SWB + wid * 8);
        #pragma unroll
        for (int j = 0; j < 4; j++) {
            unsigned long long bj = bp[j];
            acc[j * 4 + 0] = bj; acc[j * 4 + 1] = bj;
            acc[j * 4 + 2] = bj; acc[j * 4 + 3] = bj;
        }
    }

    for (int ch = 0; ch < 28; ch++) {
        if (ch < 27) { issue(ch + 1, (ch + 1) & 1); CPCOMMIT(); CPWAIT(1); }
        else         { CPWAIT(0); }
        __syncthreads();
        const float* xb = sm + XS + (ch & 1) * 1024;
        const float* wb = sm + WS + (ch & 1) * 512;
        #pragma unroll
        for (int kk = 0; kk < 8; kk++) {
            float4 xv = *reinterpret_cast<const float4*>(xb + kk * 128 + lane * 4);
            unsigned long long xq0, xq1, xq2, xq3;
            BCAST(xq0, xv.x); BCAST(xq1, xv.y); BCAST(xq2, xv.z); BCAST(xq3, xv.w);
            const ulonglong2* wp =
                reinterpret_cast<const ulonglong2*>(wb + kk * 64 + wid * 8);
            ulonglong2 wA = wp[0], wB = wp[1];
            FMA2(acc[0],  wA.x, xq0); FMA2(acc[1],  wA.x, xq1);
            FMA2(acc[2],  wA.x, xq2); FMA2(acc[3],  wA.x, xq3);
            FMA2(acc[4],  wA.y, xq0); FMA2(acc[5],  wA.y, xq1);
            FMA2(acc[6],  wA.y, xq2); FMA2(acc[7],  wA.y, xq3);
            FMA2(acc[8],  wB.x, xq0); FMA2(acc[9],  wB.x, xq1);
            FMA2(acc[10], wB.x, xq2); FMA2(acc[11], wB.x, xq3);
            FMA2(acc[12], wB.y, xq0); FMA2(acc[13], wB.y, xq1);
            FMA2(acc[14], wB.y, xq2); FMA2(acc[15], wB.y, xq3);
        }
        __syncthreads();
    }

    #pragma unroll
    for (int j = 0; j < 4; j++) {
        float lo0, hi0, lo1, hi1, lo2, hi2, lo3, hi3;
        UNPK(lo0, hi0, acc[j * 4 + 0]); UNPK(lo1, hi1, acc[j * 4 + 1]);
        UNPK(lo2, hi2, acc[j * 4 + 2]); UNPK(lo3, hi3, acc[j * 4 + 3]);
        int o = wid * 8 + 2 * j;
        *reinterpret_cast<float4*>(sm + HSO + o * 132 + lane * 4)
            = make_float4(lo0, lo1, lo2, lo3);
        *reinterpret_cast<float4*>(sm + HSO + (o + 1) * 132 + lane * 4)
            = make_float4(hi0, hi1, hi2, hi3);
    }
    __syncthreads();

    const int v = tid & 127, half = tid >> 7;
    const int obase = half * 16;

    float hv[32];
    #pragma unroll
    for (int j = 0; j < 32; j++) {
        float t = sm[HSO + j * 132 + v];
        hv[j] = t > 0.f ? t : 0.2f * t;
    }

    unsigned long long m[8];
    {
        const unsigned long long* bmp =
            reinterpret_cast<const unsigned long long*>(sm + SWB + 64 + obase);
        #pragma unroll
        for (int p = 0; p < 8; p++) m[p] = bmp[p];
    }
    #pragma unroll
    for (int j = 0; j < 32; j++) {
        unsigned long long xj; BCAST(xj, hv[j]);
        const unsigned long long* wr =
            reinterpret_cast<const unsigned long long*>(sm + SWB + 128 + j * 32 + obase);
        #pragma unroll
        for (int p = 0; p < 8; p++) FMA2(m[p], wr[p], xj);
    }
    #pragma unroll
    for (int p = 0; p < 8; p++) {
        float lo, hi; UNPK(lo, hi, m[p]);
        lo = lo > 0.f ? lo : 0.2f * lo;
        hi = hi > 0.f ? hi : 0.2f * hi;
        sm[H2S + (obase + 2 * p) * 132 + v]     = lo;
        sm[H2S + (obase + 2 * p + 1) * 132 + v] = hi;
    }
    __syncthreads();

    unsigned long long f[8];
    {
        const unsigned long long* bop =
            reinterpret_cast<const unsigned long long*>(sm + SWB + 96 + obase);
        #pragma unroll
        for (int p = 0; p < 8; p++) f[p] = bop[p];
    }
    #pragma unroll
    for (int i = 0; i < 32; i++) {
        float h2 = sm[H2S + i * 132 + v];
        unsigned long long xi; BCAST(xi, h2);
        const unsigned long long* wr =
            reinterpret_cast<const unsigned long long*>(sm + SWB + 1152 + i * 32 + obase);
        #pragma unroll
        for (int p = 0; p < 8; p++) FMA2(f[p], wr[p], xi);
    }

    float* st = g_state + ((size_t)(b * NC) << 15) + v0 + v;
    #pragma unroll
    for (int p = 0; p < 8; p++) {
        float t0, t1; UNPK(t0, t1, f[p]);
        int o = obase + 2 * p;
        float s0 = sm[HSO + (32 + o) * 132 + v];
        float s1 = sm[HSO + (33 + o) * 132 + v];
        st[(size_t)o << 15]       += 0.1f * (t0 + s0);
        st[(size_t)(o + 1) << 15] += 0.1f * (t1 + s1);
    }
}

// ---------------- channel mean ----------------

__global__ void k_final(float* __restrict__ out) {
    int b = blockIdx.y;
    int v = (blockIdx.x << 8) + threadIdx.x;
    const float* st = g_state + b * NC * VOL + v;
    float s = 0.f;
    #pragma unroll
    for (int c = 0; c < NC; c++) s += st[c << 15];
    out[b * VOL + v] = s * (1.f / 32.f);
}

// ---------------- launch ----------------

extern "C" void kernel_launch(void* const* d_in, const int* in_sizes, int n_in,
                              void* d_out, int out_size) {
    const float* z  = (const float*)d_in[0];
    const int*   y  = (const int*)d_in[1];
    const float* hw = (const float*)d_in[2];
    const float* hb = (const float*)d_in[3];
    float* out = (float*)d_out;
    (void)in_sizes; (void)n_in; (void)out_size;

    cudaFuncSetAttribute(k_residual, cudaFuncAttributeMaxDynamicSharedMemorySize,
                         SM_FLOATS * 4);

    k_norm<<<4, 256>>>(z);
    k_init<<<dim3(128, 4), 256>>>(z);
    k_theta<<<(BATCH * KT + 255) / 256, 256>>>(y, hw, hb);

    for (int it = 0; it < 4; it++) {
        k_sobel<<<dim3(32, 4), 512>>>();
        k_fold<<<4, 256>>>();
        k_residual<<<dim3(256, 4), 256, SM_FLOATS * 4>>>();
    }
    k_final<<<dim3(128, 4), 256>>>(out);
}

// round 4
// speedup vs baseline: 2.5213x; 1.0033x over previous
#include <cuda_runtime.h>
#include <cuda_bf16.h>
#include <cstdint>

#define BATCH 4
#define NC 32
#define CIN 224
#define VOL 32768
#define KT 16512

__device__ float  g_state[BATCH * NC * VOL];
__device__ float  g_feat [BATCH * CIN * VOL];
__device__ double g_sumd [BATCH * CIN];
__device__ double g_sqd  [BATCH * CIN];
__device__ float  g_zn   [BATCH];
__device__ float  g_theta[BATCH * KT];
__device__ float  g_w    [BATCH * KT];

// offsets (floats) inside per-batch g_w block
#define WC_OFF  0       // [224][64]: 0..31 = W_in', 32..63 = W_sh'
#define B64_OFF 14336
#define WM_OFF  14400   // wm[j*32+i] = w_mid[i][j]
#define BM_OFF  15424
#define WO_OFF  15456   // wo[i*32+o] = w_out[o][i]
#define BO_OFF  16480

#define FMA2(acc, w, x) asm("fma.rn.f32x2 %0, %1, %2, %0;" : "+l"(acc) : "l"(w), "l"(x))
#define BCAST(d, f)     asm("mov.b64 %0, {%1, %1};" : "=l"(d) : "f"(f))
#define UNPK(lo, hi, q) asm("mov.b64 {%0, %1}, %2;" : "=f"(lo), "=f"(hi) : "l"(q))
#define CPA16(dst, src) asm volatile("cp.async.cg.shared.global [%0], [%1], 16;" :: "r"(dst), "l"(src))
#define CPCOMMIT()      asm volatile("cp.async.commit_group;")
#define CPWAIT(n)       asm volatile("cp.async.wait_group %0;" :: "n"(n))

// ---------------- setup ----------------

__global__ void k_norm(const float* __restrict__ z) {
    int b = blockIdx.x, t = threadIdx.x;
    float v0 = z[b * 512 + t], v1 = z[b * 512 + 256 + t];
    float s = v0 * v0 + v1 * v1;
    #pragma unroll
    for (int o = 16; o; o >>= 1) s += __shfl_down_sync(~0u, s, o);
    __shared__ float sh[8];
    if ((t & 31) == 0) sh[t >> 5] = s;
    __syncthreads();
    if (t < 8) {
        float x = sh[t];
        #pragma unroll
        for (int o = 4; o; o >>= 1) x += __shfl_down_sync(0xffu, x, o);
        if (t == 0) g_zn[b] = fmaxf(sqrtf(x), 1e-12f);
    }
}

__global__ void k_init(const float* __restrict__ z) {
    int b = blockIdx.y;
    int v = (blockIdx.x << 8) + threadIdx.x;
    float val = 0.f;
    if (v < 512) val = z[b * 512 + v] / g_zn[b];
    #pragma unroll
    for (int c = 0; c < NC; c++) g_state[((b * NC + c) << 15) + v] = val;
}

__global__ void k_theta(const int* __restrict__ y, const float* __restrict__ hw,
                        const float* __restrict__ hb) {
    int i = blockIdx.x * 256 + threadIdx.x;
    if (i >= BATCH * KT) return;
    int b = i / KT, k = i - b * KT;
    g_theta[i] = hw[y[b] * KT + k] + hb[k];
}

// ---------------- sobel: shfl W, smem H, register-window D; prefetched LDG ----

__global__ void __launch_bounds__(512) k_sobel() {
    __shared__ float sl[2][4][36][32];   // [buf][arr][h+2][w]
    __shared__ float red[16][14];
    const int c = blockIdx.x, b = blockIdx.y;
    const int tid = threadIdx.x;
    const int lane = tid & 31, wid = tid >> 5;
    const int h0 = wid * 2;
    const float* __restrict__ xin = g_state + ((size_t)(b * NC + c) << 15);
    float* __restrict__ featb = g_feat + (size_t)(b * CIN + c) * VOL;

    for (int i = tid; i < 1024; i += 512) {
        int w = i & 31, r = (i >> 5) & 3, arr = (i >> 7) & 3, bu = i >> 9;
        int hp = (r < 2) ? r : r + 32;
        sl[bu][arr][hp][w] = 0.f;
    }

    const float R2 = 0.70710678118654752f;
    const float S1 = 1.f + R2;

    float stat[14];
    #pragma unroll
    for (int i = 0; i < 14; i++) stat[i] = 0.f;
    float W[2][6][5];
    #pragma unroll
    for (int r = 0; r < 2; r++)
        #pragma unroll
        for (int a = 0; a < 6; a++)
            #pragma unroll
            for (int k = 0; k < 5; k++) W[r][a][k] = 0.f;

    float xc[2];
    xc[0] = xin[((h0 + 0) << 5) + lane];
    xc[1] = xin[((h0 + 1) << 5) + lane];

    __syncthreads();

    float sw3[2], dw3[2], sw5[2], dw5[2];

    #pragma unroll 2
    for (int s = 0; s < 34; s++) {
        const int bu = s & 1;
        // prefetch slice s+1
        float xn0 = 0.f, xn1 = 0.f;
        if (s + 1 < 32) {
            xn0 = xin[((s + 1) << 10) + ((h0 + 0) << 5) + lane];
            xn1 = xin[((s + 1) << 10) + ((h0 + 1) << 5) + lane];
        }
        if (s < 32) {
            #pragma unroll
            for (int r = 0; r < 2; r++) {
                float xv = xc[r];
                stat[0] += xv; stat[1] += xv * xv;
                float xm1 = __shfl_up_sync(~0u, xv, 1);   if (lane == 0)  xm1 = 0.f;
                float xm2 = __shfl_up_sync(~0u, xv, 2);   if (lane < 2)   xm2 = 0.f;
                float xp1 = __shfl_down_sync(~0u, xv, 1); if (lane == 31) xp1 = 0.f;
                float xp2 = __shfl_down_sync(~0u, xv, 2); if (lane > 29)  xp2 = 0.f;
                sw3[r] = xm1 + 2.f * xv + xp1;
                dw3[r] = xp1 - xm1;
                sw5[r] = xm2 + xp2 + S1 * (xm1 + xp1) + 2.f * xv;
                dw5[r] = (xp2 - xm2) + R2 * (xp1 - xm1);
                int hp = h0 + r + 2;
                sl[bu][0][hp][lane] = sw3[r];
                sl[bu][1][hp][lane] = dw3[r];
                sl[bu][2][hp][lane] = sw5[r];
                sl[bu][3][hp][lane] = dw5[r];
            }
        }
        xc[0] = xn0; xc[1] = xn1;
        __syncthreads();
        #pragma unroll
        for (int r = 0; r < 2; r++) {
            float a30, a31, a32, a50, a51, a52;
            if (s < 32) {
                int hp = h0 + r + 2;
                float s3m = sl[bu][0][hp - 1][lane], s3p = sl[bu][0][hp + 1][lane];
                float d3m = sl[bu][1][hp - 1][lane], d3p = sl[bu][1][hp + 1][lane];
                float s5m2 = sl[bu][2][hp - 2][lane], s5m1 = sl[bu][2][hp - 1][lane];
                float s5p1 = sl[bu][2][hp + 1][lane], s5p2 = sl[bu][2][hp + 2][lane];
                float d5m2 = sl[bu][3][hp - 2][lane], d5m1 = sl[bu][3][hp - 1][lane];
                float d5p1 = sl[bu][3][hp + 1][lane], d5p2 = sl[bu][3][hp + 2][lane];
                a30 = d3m + 2.f * dw3[r] + d3p;
                a31 = s3p - s3m;
                a32 = s3m + 2.f * sw3[r] + s3p;
                a50 = d5m2 + d5p2 + S1 * (d5m1 + d5p1) + 2.f * dw5[r];
                a51 = (s5p2 - s5m2) + R2 * (s5p1 - s5m1);
                a52 = s5m2 + s5p2 + S1 * (s5m1 + s5p1) + 2.f * sw5[r];
            } else {
                a30 = a31 = a32 = a50 = a51 = a52 = 0.f;
            }
            #pragma unroll
            for (int a = 0; a < 6; a++) {
                W[r][a][0] = W[r][a][1]; W[r][a][1] = W[r][a][2];
                W[r][a][2] = W[r][a][3]; W[r][a][3] = W[r][a][4];
            }
            W[r][0][4] = a32; W[r][1][4] = a31; W[r][2][4] = a30;
            W[r][3][4] = a52; W[r][4][4] = a51; W[r][5][4] = a50;

            if (s >= 2) {
                int dc = s - 2;
                float o1 = W[r][0][3] - W[r][0][1];
                float o2 = W[r][1][1] + 2.f * W[r][1][2] + W[r][1][3];
                float o3 = W[r][2][1] + 2.f * W[r][2][2] + W[r][2][3];
                float o4 = (W[r][3][4] - W[r][3][0]) + R2 * (W[r][3][3] - W[r][3][1]);
                float o5 = W[r][4][0] + W[r][4][4] + S1 * (W[r][4][1] + W[r][4][3]) + 2.f * W[r][4][2];
                float o6 = W[r][5][0] + W[r][5][4] + S1 * (W[r][5][1] + W[r][5][3]) + 2.f * W[r][5][2];
                int v = (dc << 10) + ((h0 + r) << 5) + lane;
                featb[(size_t)32 * VOL + v]  = o1;
                featb[(size_t)64 * VOL + v]  = o2;
                featb[(size_t)96 * VOL + v]  = o3;
                featb[(size_t)128 * VOL + v] = o4;
                featb[(size_t)160 * VOL + v] = o5;
                featb[(size_t)192 * VOL + v] = o6;
                stat[2]  += o1; stat[3]  += o1 * o1;
                stat[4]  += o2; stat[5]  += o2 * o2;
                stat[6]  += o3; stat[7]  += o3 * o3;
                stat[8]  += o4; stat[9]  += o4 * o4;
                stat[10] += o5; stat[11] += o5 * o5;
                stat[12] += o6; stat[13] += o6 * o6;
            }
        }
    }

    #pragma unroll
    for (int i = 0; i < 14; i++) {
        float v = stat[i];
        #pragma unroll
        for (int o = 16; o; o >>= 1) v += __shfl_down_sync(~0u, v, o);
        stat[i] = v;
    }
    if (lane == 0)
        #pragma unroll
        for (int i = 0; i < 14; i++) red[wid][i] = stat[i];
    __syncthreads();
    if (tid < 14) {
        double acc = 0.0;
        #pragma unroll
        for (int k = 0; k < 16; k++) acc += (double)red[k][tid];
        int g = tid >> 1;
        if (tid & 1) g_sqd [b * CIN + g * 32 + c] = acc;
        else         g_sumd[b * CIN + g * 32 + c] = acc;
    }
}

// ---------------- fold norm into weights (warp-parallel) ----------------

__global__ void k_fold() {
    int b = blockIdx.x, tid = threadIdx.x;
    int lane = tid & 31, wid = tid >> 5;
    __shared__ float smean[CIN], srs[CIN];
    if (tid < CIN) {
        double m = g_sumd[b * CIN + tid] * (1.0 / 32768.0);
        double var = g_sqd[b * CIN + tid] * (1.0 / 32768.0) - m * m;
        smean[tid] = (float)m;
        srs[tid] = (float)rsqrt(var + 1e-5);
    }
    __syncthreads();
    const float* th = g_theta + b * KT;
    float* w = g_w + b * KT;
    #pragma unroll
    for (int j = 0; j < 8; j++) {
        int o = wid * 8 + j;
        int off = (o < 32) ? o * 224 : 9312 + (o - 32) * 224;
        float corr = 0.f;
        #pragma unroll
        for (int q = 0; q < 7; q++) {
            int cc = lane + q * 32;
            float wv = th[off + cc] * srs[cc];
            w[WC_OFF + cc * 64 + o] = wv;
            corr += wv * smean[cc];
        }
        #pragma unroll
        for (int d = 16; d; d >>= 1) corr += __shfl_down_sync(~0u, corr, d);
        if (lane == 0) {
            float braw = (o < 32) ? th[7168 + o] : th[16480 + o - 32];
            w[B64_OFF + o] = braw - corr;
        }
    }
    for (int i = tid; i < 1024; i += 256) {
        int r = i >> 5, cc = i & 31;
        w[WM_OFF + cc * 32 + r] = th[7200 + r * 32 + cc];
        w[WO_OFF + cc * 32 + r] = th[8256 + r * 32 + cc];
    }
    if (tid < 32) {
        w[BM_OFF + tid] = th[8224 + tid];
        w[BO_OFF + tid] = th[9280 + tid];
    }
}

// ---------------- register-blocked residual MLP ----------------
// block: 64 outputs x 128 voxels, 256 threads; thread = 8 out x 4 vox micro-tile
// smem union: XS/WS (stage 1) overlaps HSO (epilogue+stage 2)

#define XS   0       // [4][8][128]
#define WS   4096    // [4][8][64]
#define HSO  0       // [64][132] (after stage-1 loop)
#define SWB  8448    // b64[64] | bm[32] | bo[32] | wm[1024] | wo[1024]
#define H2S  10624   // [32][129]
#define SM_FLOATS 14752

__global__ void __launch_bounds__(256, 3) k_residual() {
    extern __shared__ float sm[];
    const int tid = threadIdx.x;
    const int wid = tid >> 5, lane = tid & 31;
    const int b = blockIdx.y;
    const int v0 = blockIdx.x << 7;
    const float* gw = g_w + b * KT;
    unsigned swa = (unsigned)__cvta_generic_to_shared(sm);

    if (tid < 64)  sm[SWB + tid]       = gw[B64_OFF + tid];
    if (tid < 32)  sm[SWB + 64 + tid]  = gw[BM_OFF + tid];
    if (tid >= 32 && tid < 64) sm[SWB + 96 + (tid - 32)] = gw[BO_OFF + tid - 32];
    for (int i = tid; i < 1024; i += 256) sm[SWB + 128 + i]  = gw[WM_OFF + i];
    for (int i = tid; i < 1024; i += 256) sm[SWB + 1152 + i] = gw[WO_OFF + i];

    const int ckk = tid >> 5, clw = tid & 31;
    auto issue = [&](int ch) {
        int buf = ch & 3;
        int cc = ch * 8 + ckk;
        const float* xsrc = (cc < 32)
            ? g_state + ((size_t)(b * NC + cc) << 15) + v0 + clw * 4
            : g_feat  + ((size_t)(b * CIN + cc) << 15) + v0 + clw * 4;
        CPA16(swa + (XS + buf * 1024 + ckk * 128 + clw * 4) * 4, xsrc);
        if (tid < 128) {
            const float* wsrc = gw + WC_OFF + ch * 512 + tid * 4;
            CPA16(swa + (WS + buf * 512 + tid * 4) * 4, wsrc);
        }
    };

    issue(0); CPCOMMIT();
    issue(1); CPCOMMIT();
    __syncthreads();   // small weights visible

    unsigned long long acc[16];
    {
        const unsigned long long* bp =
            reinterpret_cast<const unsigned long long*>(sm + SWB + wid * 8);
        #pragma unroll
        for (int j = 0; j < 4; j++) {
            unsigned long long bj = bp[j];
            acc[j * 4 + 0] = bj; acc[j * 4 + 1] = bj;
            acc[j * 4 + 2] = bj; acc[j * 4 + 3] = bj;
        }
    }

    for (int ch = 0; ch < 28; ch++) {
        if (ch <= 25)      { issue(ch + 2); CPCOMMIT(); CPWAIT(2); }
        else if (ch == 26) { CPWAIT(1); }
        else               { CPWAIT(0); }
        __syncthreads();
        const float* xb = sm + XS + (ch & 3) * 1024;
        const float* wb = sm + WS + (ch & 3) * 512;
        #pragma unroll
        for (int kk = 0; kk < 8; kk++) {
            float4 xv = *reinterpret_cast<const float4*>(xb + kk * 128 + lane * 4);
            unsigned long long xq0, xq1, xq2, xq3;
            BCAST(xq0, xv.x); BCAST(xq1, xv.y); BCAST(xq2, xv.z); BCAST(xq3, xv.w);
            const ulonglong2* wp =
                reinterpret_cast<const ulonglong2*>(wb + kk * 64 + wid * 8);
            ulonglong2 wA = wp[0], wB = wp[1];
            FMA2(acc[0],  wA.x, xq0); FMA2(acc[1],  wA.x, xq1);
            FMA2(acc[2],  wA.x, xq2); FMA2(acc[3],  wA.x, xq3);
            FMA2(acc[4],  wA.y, xq0); FMA2(acc[5],  wA.y, xq1);
            FMA2(acc[6],  wA.y, xq2); FMA2(acc[7],  wA.y, xq3);
            FMA2(acc[8],  wB.x, xq0); FMA2(acc[9],  wB.x, xq1);
            FMA2(acc[10], wB.x, xq2); FMA2(acc[11], wB.x, xq3);
            FMA2(acc[12], wB.y, xq0); FMA2(acc[13], wB.y, xq1);
            FMA2(acc[14], wB.y, xq2); FMA2(acc[15], wB.y, xq3);
        }
    }
    __syncthreads();   // XS/WS dead; HSO may be written

    #pragma unroll
    for (int j = 0; j < 4; j++) {
        float lo0, hi0, lo1, hi1, lo2, hi2, lo3, hi3;
        UNPK(lo0, hi0, acc[j * 4 + 0]); UNPK(lo1, hi1, acc[j * 4 + 1]);
        UNPK(lo2, hi2, acc[j * 4 + 2]); UNPK(lo3, hi3, acc[j * 4 + 3]);
        int o = wid * 8 + 2 * j;
        *reinterpret_cast<float4*>(sm + HSO + o * 132 + lane * 4)
            = make_float4(lo0, lo1, lo2, lo3);
        *reinterpret_cast<float4*>(sm + HSO + (o + 1) * 132 + lane * 4)
            = make_float4(hi0, hi1, hi2, hi3);
    }
    __syncthreads();

    const int v = tid & 127, half = tid >> 7;
    const int obase = half * 16;

    float hv[32];
    #pragma unroll
    for (int j = 0; j < 32; j++) {
        float t = sm[HSO + j * 132 + v];
        hv[j] = t > 0.f ? t : 0.2f * t;
    }

    unsigned long long m[8];
    {
        const unsigned long long* bmp =
            reinterpret_cast<const unsigned long long*>(sm + SWB + 64 + obase);
        #pragma unroll
        for (int p = 0; p < 8; p++) m[p] = bmp[p];
    }
    #pragma unroll
    for (int j = 0; j < 32; j++) {
        unsigned long long xj; BCAST(xj, hv[j]);
        const unsigned long long* wr =
            reinterpret_cast<const unsigned long long*>(sm + SWB + 128 + j * 32 + obase);
        #pragma unroll
        for (int p = 0; p < 8; p++) FMA2(m[p], wr[p], xj);
    }
    #pragma unroll
    for (int p = 0; p < 8; p++) {
        float lo, hi; UNPK(lo, hi, m[p]);
        lo = lo > 0.f ? lo : 0.2f * lo;
        hi = hi > 0.f ? hi : 0.2f * hi;
        sm[H2S + (obase + 2 * p) * 129 + v]     = lo;
        sm[H2S + (obase + 2 * p + 1) * 129 + v] = hi;
    }
    __syncthreads();

    unsigned long long f[8];
    {
        const unsigned long long* bop =
            reinterpret_cast<const unsigned long long*>(sm + SWB + 96 + obase);
        #pragma unroll
        for (int p = 0; p < 8; p++) f[p] = bop[p];
    }
    #pragma unroll
    for (int i = 0; i < 32; i++) {
        float h2 = sm[H2S + i * 129 + v];
        unsigned long long xi; BCAST(xi, h2);
        const unsigned long long* wr =
            reinterpret_cast<const unsigned long long*>(sm + SWB + 1152 + i * 32 + obase);
        #pragma unroll
        for (int p = 0; p < 8; p++) FMA2(f[p], wr[p], xi);
    }

    float* st = g_state + ((size_t)(b * NC) << 15) + v0 + v;
    #pragma unroll
    for (int p = 0; p < 8; p++) {
        float t0, t1; UNPK(t0, t1, f[p]);
        int o = obase + 2 * p;
        float s0 = sm[HSO + (32 + o) * 132 + v];
        float s1 = sm[HSO + (33 + o) * 132 + v];
        st[(size_t)o << 15]       += 0.1f * (t0 + s0);
        st[(size_t)(o + 1) << 15] += 0.1f * (t1 + s1);
    }
}

// ---------------- channel mean ----------------

__global__ void k_final(float* __restrict__ out) {
    int b = blockIdx.y;
    int v = (blockIdx.x << 8) + threadIdx.x;
    const float* st = g_state + b * NC * VOL + v;
    float s = 0.f;
    #pragma unroll
    for (int c = 0; c < NC; c++) s += st[c << 15];
    out[b * VOL + v] = s * (1.f / 32.f);
}

// ---------------- launch ----------------

extern "C" void kernel_launch(void* const* d_in, const int* in_sizes, int n_in,
                              void* d_out, int out_size) {
    const float* z  = (const float*)d_in[0];
    const int*   y  = (const int*)d_in[1];
    const float* hw = (const float*)d_in[2];
    const float* hb = (const float*)d_in[3];
    float* out = (float*)d_out;
    (void)in_sizes; (void)n_in; (void)out_size;

    cudaFuncSetAttribute(k_residual, cudaFuncAttributeMaxDynamicSharedMemorySize,
                         SM_FLOATS * 4);

    k_norm<<<4, 256>>>(z);
    k_init<<<dim3(128, 4), 256>>>(z);
    k_theta<<<(BATCH * KT + 255) / 256, 256>>>(y, hw, hb);

    for (int it = 0; it < 4; it++) {
        k_sobel<<<dim3(32, 4), 512>>>();
        k_fold<<<4, 256>>>();
        k_residual<<<dim3(256, 4), 256, SM_FLOATS * 4>>>();
    }
    k_final<<<dim3(128, 4), 256>>>(out);
}

// round 5
// speedup vs baseline: 2.6611x; 1.0554x over previous
#include <cuda_runtime.h>
#include <cuda_bf16.h>
#include <cstdint>

#define BATCH 4
#define NC 32
#define CIN 224
#define VOL 32768
#define KT 16512

__device__ float  g_state[BATCH * NC * VOL];
__device__ float  g_feat [BATCH * CIN * VOL];
__device__ double g_sumd [BATCH * CIN];
__device__ double g_sqd  [BATCH * CIN];
__device__ float  g_zn   [BATCH];
__device__ float  g_theta[BATCH * KT];
__device__ float  g_w    [BATCH * KT];

// offsets (floats) inside per-batch g_w block
#define WC_OFF  0       // [224][64]: 0..31 = W_in', 32..63 = W_sh'
#define B64_OFF 14336
#define WM_OFF  14400   // wm[j*32+i] = w_mid[i][j]
#define BM_OFF  15424
#define WO_OFF  15456   // wo[i*32+o] = w_out[o][i]
#define BO_OFF  16480

#define FMA2(acc, w, x) asm("fma.rn.f32x2 %0, %1, %2, %0;" : "+l"(acc) : "l"(w), "l"(x))
#define BCAST(d, f)     asm("mov.b64 %0, {%1, %1};" : "=l"(d) : "f"(f))
#define UNPK(lo, hi, q) asm("mov.b64 {%0, %1}, %2;" : "=f"(lo), "=f"(hi) : "l"(q))
#define CPA16(dst, src) asm volatile("cp.async.cg.shared.global [%0], [%1], 16;" :: "r"(dst), "l"(src))
#define CPCOMMIT()      asm volatile("cp.async.commit_group;")
#define CPWAIT(n)       asm volatile("cp.async.wait_group %0;" :: "n"(n))

// ---------------- setup ----------------

__global__ void k_norm(const float* __restrict__ z) {
    int b = blockIdx.x, t = threadIdx.x;
    float v0 = z[b * 512 + t], v1 = z[b * 512 + 256 + t];
    float s = v0 * v0 + v1 * v1;
    #pragma unroll
    for (int o = 16; o; o >>= 1) s += __shfl_down_sync(~0u, s, o);
    __shared__ float sh[8];
    if ((t & 31) == 0) sh[t >> 5] = s;
    __syncthreads();
    if (t < 8) {
        float x = sh[t];
        #pragma unroll
        for (int o = 4; o; o >>= 1) x += __shfl_down_sync(0xffu, x, o);
        if (t == 0) g_zn[b] = fmaxf(sqrtf(x), 1e-12f);
    }
}

__global__ void k_init(const float* __restrict__ z) {
    int b = blockIdx.y;
    int v = (blockIdx.x << 8) + threadIdx.x;
    float val = 0.f;
    if (v < 512) val = z[b * 512 + v] / g_zn[b];
    #pragma unroll
    for (int c = 0; c < NC; c++) g_state[((b * NC + c) << 15) + v] = val;
}

__global__ void k_theta(const int* __restrict__ y, const float* __restrict__ hw,
                        const float* __restrict__ hb) {
    int i = blockIdx.x * 256 + threadIdx.x;
    if (i >= BATCH * KT) return;
    int b = i / KT, k = i - b * KT;
    g_theta[i] = hw[y[b] * KT + k] + hb[k];
}

// ---------------- sobel: shfl W, smem H, register-window D; prefetched LDG ----

__global__ void __launch_bounds__(512) k_sobel() {
    __shared__ float sl[2][4][36][32];   // [buf][arr][h+2][w]
    __shared__ float red[16][14];
    const int c = blockIdx.x, b = blockIdx.y;
    const int tid = threadIdx.x;
    const int lane = tid & 31, wid = tid >> 5;
    const int h0 = wid * 2;
    const float* __restrict__ xin = g_state + ((size_t)(b * NC + c) << 15);
    float* __restrict__ featb = g_feat + (size_t)(b * CIN + c) * VOL;

    for (int i = tid; i < 1024; i += 512) {
        int w = i & 31, r = (i >> 5) & 3, arr = (i >> 7) & 3, bu = i >> 9;
        int hp = (r < 2) ? r : r + 32;
        sl[bu][arr][hp][w] = 0.f;
    }

    const float R2 = 0.70710678118654752f;
    const float S1 = 1.f + R2;

    float stat[14];
    #pragma unroll
    for (int i = 0; i < 14; i++) stat[i] = 0.f;
    float W[2][6][5];
    #pragma unroll
    for (int r = 0; r < 2; r++)
        #pragma unroll
        for (int a = 0; a < 6; a++)
            #pragma unroll
            for (int k = 0; k < 5; k++) W[r][a][k] = 0.f;

    float xc[2];
    xc[0] = xin[((h0 + 0) << 5) + lane];
    xc[1] = xin[((h0 + 1) << 5) + lane];

    __syncthreads();

    float sw3[2], dw3[2], sw5[2], dw5[2];

    #pragma unroll 2
    for (int s = 0; s < 34; s++) {
        const int bu = s & 1;
        float xn0 = 0.f, xn1 = 0.f;
        if (s + 1 < 32) {
            xn0 = xin[((s + 1) << 10) + ((h0 + 0) << 5) + lane];
            xn1 = xin[((s + 1) << 10) + ((h0 + 1) << 5) + lane];
        }
        if (s < 32) {
            #pragma unroll
            for (int r = 0; r < 2; r++) {
                float xv = xc[r];
                stat[0] += xv; stat[1] += xv * xv;
                float xm1 = __shfl_up_sync(~0u, xv, 1);   if (lane == 0)  xm1 = 0.f;
                float xm2 = __shfl_up_sync(~0u, xv, 2);   if (lane < 2)   xm2 = 0.f;
                float xp1 = __shfl_down_sync(~0u, xv, 1); if (lane == 31) xp1 = 0.f;
                float xp2 = __shfl_down_sync(~0u, xv, 2); if (lane > 29)  xp2 = 0.f;
                sw3[r] = xm1 + 2.f * xv + xp1;
                dw3[r] = xp1 - xm1;
                sw5[r] = xm2 + xp2 + S1 * (xm1 + xp1) + 2.f * xv;
                dw5[r] = (xp2 - xm2) + R2 * (xp1 - xm1);
                int hp = h0 + r + 2;
                sl[bu][0][hp][lane] = sw3[r];
                sl[bu][1][hp][lane] = dw3[r];
                sl[bu][2][hp][lane] = sw5[r];
                sl[bu][3][hp][lane] = dw5[r];
            }
        }
        xc[0] = xn0; xc[1] = xn1;
        __syncthreads();
        #pragma unroll
        for (int r = 0; r < 2; r++) {
            float a30, a31, a32, a50, a51, a52;
            if (s < 32) {
                int hp = h0 + r + 2;
                float s3m = sl[bu][0][hp - 1][lane], s3p = sl[bu][0][hp + 1][lane];
                float d3m = sl[bu][1][hp - 1][lane], d3p = sl[bu][1][hp + 1][lane];
                float s5m2 = sl[bu][2][hp - 2][lane], s5m1 = sl[bu][2][hp - 1][lane];
                float s5p1 = sl[bu][2][hp + 1][lane], s5p2 = sl[bu][2][hp + 2][lane];
                float d5m2 = sl[bu][3][hp - 2][lane], d5m1 = sl[bu][3][hp - 1][lane];
                float d5p1 = sl[bu][3][hp + 1][lane], d5p2 = sl[bu][3][hp + 2][lane];
                a30 = d3m + 2.f * dw3[r] + d3p;
                a31 = s3p - s3m;
                a32 = s3m + 2.f * sw3[r] + s3p;
                a50 = d5m2 + d5p2 + S1 * (d5m1 + d5p1) + 2.f * dw5[r];
                a51 = (s5p2 - s5m2) + R2 * (s5p1 - s5m1);
                a52 = s5m2 + s5p2 + S1 * (s5m1 + s5p1) + 2.f * sw5[r];
            } else {
                a30 = a31 = a32 = a50 = a51 = a52 = 0.f;
            }
            #pragma unroll
            for (int a = 0; a < 6; a++) {
                W[r][a][0] = W[r][a][1]; W[r][a][1] = W[r][a][2];
                W[r][a][2] = W[r][a][3]; W[r][a][3] = W[r][a][4];
            }
            W[r][0][4] = a32; W[r][1][4] = a31; W[r][2][4] = a30;
            W[r][3][4] = a52; W[r][4][4] = a51; W[r][5][4] = a50;

            if (s >= 2) {
                int dc = s - 2;
                float o1 = W[r][0][3] - W[r][0][1];
                float o2 = W[r][1][1] + 2.f * W[r][1][2] + W[r][1][3];
                float o3 = W[r][2][1] + 2.f * W[r][2][2] + W[r][2][3];
                float o4 = (W[r][3][4] - W[r][3][0]) + R2 * (W[r][3][3] - W[r][3][1]);
                float o5 = W[r][4][0] + W[r][4][4] + S1 * (W[r][4][1] + W[r][4][3]) + 2.f * W[r][4][2];
                float o6 = W[r][5][0] + W[r][5][4] + S1 * (W[r][5][1] + W[r][5][3]) + 2.f * W[r][5][2];
                int v = (dc << 10) + ((h0 + r) << 5) + lane;
                featb[(size_t)32 * VOL + v]  = o1;
                featb[(size_t)64 * VOL + v]  = o2;
                featb[(size_t)96 * VOL + v]  = o3;
                featb[(size_t)128 * VOL + v] = o4;
                featb[(size_t)160 * VOL + v] = o5;
                featb[(size_t)192 * VOL + v] = o6;
                stat[2]  += o1; stat[3]  += o1 * o1;
                stat[4]  += o2; stat[5]  += o2 * o2;
                stat[6]  += o3; stat[7]  += o3 * o3;
                stat[8]  += o4; stat[9]  += o4 * o4;
                stat[10] += o5; stat[11] += o5 * o5;
                stat[12] += o6; stat[13] += o6 * o6;
            }
        }
    }

    #pragma unroll
    for (int i = 0; i < 14; i++) {
        float v = stat[i];
        #pragma unroll
        for (int o = 16; o; o >>= 1) v += __shfl_down_sync(~0u, v, o);
        stat[i] = v;
    }
    if (lane == 0)
        #pragma unroll
        for (int i = 0; i < 14; i++) red[wid][i] = stat[i];
    __syncthreads();
    if (tid < 14) {
        double acc = 0.0;
        #pragma unroll
        for (int k = 0; k < 16; k++) acc += (double)red[k][tid];
        int g = tid >> 1;
        if (tid & 1) g_sqd [b * CIN + g * 32 + c] = acc;
        else         g_sumd[b * CIN + g * 32 + c] = acc;
    }
}

// ---------------- fold norm into weights (warp-parallel) ----------------

__global__ void k_fold() {
    int b = blockIdx.x, tid = threadIdx.x;
    int lane = tid & 31, wid = tid >> 5;
    __shared__ float smean[CIN], srs[CIN];
    if (tid < CIN) {
        double m = g_sumd[b * CIN + tid] * (1.0 / 32768.0);
        double var = g_sqd[b * CIN + tid] * (1.0 / 32768.0) - m * m;
        smean[tid] = (float)m;
        srs[tid] = (float)rsqrt(var + 1e-5);
    }
    __syncthreads();
    const float* th = g_theta + b * KT;
    float* w = g_w + b * KT;
    #pragma unroll
    for (int j = 0; j < 8; j++) {
        int o = wid * 8 + j;
        int off = (o < 32) ? o * 224 : 9312 + (o - 32) * 224;
        float corr = 0.f;
        #pragma unroll
        for (int q = 0; q < 7; q++) {
            int cc = lane + q * 32;
            float wv = th[off + cc] * srs[cc];
            w[WC_OFF + cc * 64 + o] = wv;
            corr += wv * smean[cc];
        }
        #pragma unroll
        for (int d = 16; d; d >>= 1) corr += __shfl_down_sync(~0u, corr, d);
        if (lane == 0) {
            float braw = (o < 32) ? th[7168 + o] : th[16480 + o - 32];
            w[B64_OFF + o] = braw - corr;
        }
    }
    for (int i = tid; i < 1024; i += 256) {
        int r = i >> 5, cc = i & 31;
        w[WM_OFF + cc * 32 + r] = th[7200 + r * 32 + cc];
        w[WO_OFF + cc * 32 + r] = th[8256 + r * 32 + cc];
    }
    if (tid < 32) {
        w[BM_OFF + tid] = th[8224 + tid];
        w[BO_OFF + tid] = th[9280 + tid];
    }
}

// ---------------- register-blocked residual MLP ----------------
// block: 64 outputs x 128 voxels, 256 threads; thread = 8 out x 4 vox micro-tile
// 16-channel chunks, 3-buffer cp.async ring, 1 barrier per chunk

#define XS   0       // [3][16][128] = 6144
#define WS   6144    // [3][16][64]  = 3072
#define HSO  0       // [64][132] = 8448 (union over XS/WS after stage 1)
#define SWB  9216    // b64[64] | bm[32] | bo[32] | wm[1024] | wo[1024] = 2176
#define H2S  11392   // [32][129] = 4128
#define SM_FLOATS 15520

__global__ void __launch_bounds__(256) k_residual() {
    extern __shared__ float sm[];
    const int tid = threadIdx.x;
    const int wid = tid >> 5, lane = tid & 31;
    const int b = blockIdx.y;
    const int v0 = blockIdx.x << 7;
    const float* gw = g_w + b * KT;
    unsigned swa = (unsigned)__cvta_generic_to_shared(sm);

    if (tid < 64)  sm[SWB + tid]       = gw[B64_OFF + tid];
    if (tid < 32)  sm[SWB + 64 + tid]  = gw[BM_OFF + tid];
    if (tid >= 32 && tid < 64) sm[SWB + 96 + (tid - 32)] = gw[BO_OFF + tid - 32];
    for (int i = tid; i < 1024; i += 256) sm[SWB + 128 + i]  = gw[WM_OFF + i];
    for (int i = tid; i < 1024; i += 256) sm[SWB + 1152 + i] = gw[WO_OFF + i];

    // chunk = 16 channels: X 16x128 (512 float4, 2/thread), W 16x64 (256 float4, 1/thread)
    const int xrow0 = tid >> 5, xq0w = tid & 31;          // first float4: row 0..7
    const int xrow1 = 8 + (tid >> 5), xq1w = tid & 31;    // second: row 8..15
    auto issue = [&](int ch) {
        int buf = ch % 3;
        int cc0 = ch * 16 + xrow0;
        const float* xsrc0 = (cc0 < 32)
            ? g_state + ((size_t)(b * NC + cc0) << 15) + v0 + xq0w * 4
            : g_feat  + ((size_t)(b * CIN + cc0) << 15) + v0 + xq0w * 4;
        CPA16(swa + (XS + buf * 2048 + xrow0 * 128 + xq0w * 4) * 4, xsrc0);
        int cc1 = ch * 16 + xrow1;
        const float* xsrc1 = (cc1 < 32)
            ? g_state + ((size_t)(b * NC + cc1) << 15) + v0 + xq1w * 4
            : g_feat  + ((size_t)(b * CIN + cc1) << 15) + v0 + xq1w * 4;
        CPA16(swa + (XS + buf * 2048 + xrow1 * 128 + xq1w * 4) * 4, xsrc1);
        const float* wsrc = gw + WC_OFF + ch * 1024 + tid * 4;
        CPA16(swa + (WS + buf * 1024 + tid * 4) * 4, wsrc);
    };

    issue(0); CPCOMMIT();
    issue(1); CPCOMMIT();

    unsigned long long acc[16];

    for (int ch = 0; ch < 14; ch++) {
        if (ch < 13) CPWAIT(1); else CPWAIT(0);
        __syncthreads();
        if (ch == 0) {
            const unsigned long long* bp =
                reinterpret_cast<const unsigned long long*>(sm + SWB + wid * 8);
            #pragma unroll
            for (int j = 0; j < 4; j++) {
                unsigned long long bj = bp[j];
                acc[j * 4 + 0] = bj; acc[j * 4 + 1] = bj;
                acc[j * 4 + 2] = bj; acc[j * 4 + 3] = bj;
            }
        }
        if (ch + 2 < 14) { issue(ch + 2); CPCOMMIT(); }
        const float* xb = sm + XS + (ch % 3) * 2048;
        const float* wb = sm + WS + (ch % 3) * 1024;
        #pragma unroll
        for (int kk = 0; kk < 16; kk++) {
            float4 xv = *reinterpret_cast<const float4*>(xb + kk * 128 + lane * 4);
            unsigned long long xq0, xq1, xq2, xq3;
            BCAST(xq0, xv.x); BCAST(xq1, xv.y); BCAST(xq2, xv.z); BCAST(xq3, xv.w);
            const ulonglong2* wp =
                reinterpret_cast<const ulonglong2*>(wb + kk * 64 + wid * 8);
            ulonglong2 wA = wp[0], wB = wp[1];
            FMA2(acc[0],  wA.x, xq0); FMA2(acc[1],  wA.x, xq1);
            FMA2(acc[2],  wA.x, xq2); FMA2(acc[3],  wA.x, xq3);
            FMA2(acc[4],  wA.y, xq0); FMA2(acc[5],  wA.y, xq1);
            FMA2(acc[6],  wA.y, xq2); FMA2(acc[7],  wA.y, xq3);
            FMA2(acc[8],  wB.x, xq0); FMA2(acc[9],  wB.x, xq1);
            FMA2(acc[10], wB.x, xq2); FMA2(acc[11], wB.x, xq3);
            FMA2(acc[12], wB.y, xq0); FMA2(acc[13], wB.y, xq1);
            FMA2(acc[14], wB.y, xq2); FMA2(acc[15], wB.y, xq3);
        }
    }
    __syncthreads();   // XS/WS dead; HSO may be written

    #pragma unroll
    for (int j = 0; j < 4; j++) {
        float lo0, hi0, lo1, hi1, lo2, hi2, lo3, hi3;
        UNPK(lo0, hi0, acc[j * 4 + 0]); UNPK(lo1, hi1, acc[j * 4 + 1]);
        UNPK(lo2, hi2, acc[j * 4 + 2]); UNPK(lo3, hi3, acc[j * 4 + 3]);
        int o = wid * 8 + 2 * j;
        *reinterpret_cast<float4*>(sm + HSO + o * 132 + lane * 4)
            = make_float4(lo0, lo1, lo2, lo3);
        *reinterpret_cast<float4*>(sm + HSO + (o + 1) * 132 + lane * 4)
            = make_float4(hi0, hi1, hi2, hi3);
    }
    __syncthreads();

    const int v = tid & 127, half = tid >> 7;
    const int obase = half * 16;

    float hv[32];
    #pragma unroll
    for (int j = 0; j < 32; j++) {
        float t = sm[HSO + j * 132 + v];
        hv[j] = t > 0.f ? t : 0.2f * t;
    }

    unsigned long long m[8];
    {
        const unsigned long long* bmp =
            reinterpret_cast<const unsigned long long*>(sm + SWB + 64 + obase);
        #pragma unroll
        for (int p = 0; p < 8; p++) m[p] = bmp[p];
    }
    #pragma unroll
    for (int j = 0; j < 32; j++) {
        unsigned long long xj; BCAST(xj, hv[j]);
        const unsigned long long* wr =
            reinterpret_cast<const unsigned long long*>(sm + SWB + 128 + j * 32 + obase);
        #pragma unroll
        for (int p = 0; p < 8; p++) FMA2(m[p], wr[p], xj);
    }
    #pragma unroll
    for (int p = 0; p < 8; p++) {
        float lo, hi; UNPK(lo, hi, m[p]);
        lo = lo > 0.f ? lo : 0.2f * lo;
        hi = hi > 0.f ? hi : 0.2f * hi;
        sm[H2S + (obase + 2 * p) * 129 + v]     = lo;
        sm[H2S + (obase + 2 * p + 1) * 129 + v] = hi;
    }
    __syncthreads();

    unsigned long long f[8];
    {
        const unsigned long long* bop =
            reinterpret_cast<const unsigned long long*>(sm + SWB + 96 + obase);
        #pragma unroll
        for (int p = 0; p < 8; p++) f[p] = bop[p];
    }
    #pragma unroll
    for (int i = 0; i < 32; i++) {
        float h2 = sm[H2S + i * 129 + v];
        unsigned long long xi; BCAST(xi, h2);
        const unsigned long long* wr =
            reinterpret_cast<const unsigned long long*>(sm + SWB + 1152 + i * 32 + obase);
        #pragma unroll
        for (int p = 0; p < 8; p++) FMA2(f[p], wr[p], xi);
    }

    float* st = g_state + ((size_t)(b * NC) << 15) + v0 + v;
    #pragma unroll
    for (int p = 0; p < 8; p++) {
        float t0, t1; UNPK(t0, t1, f[p]);
        int o = obase + 2 * p;
        float s0 = sm[HSO + (32 + o) * 132 + v];
        float s1 = sm[HSO + (33 + o) * 132 + v];
        st[(size_t)o << 15]       += 0.1f * (t0 + s0);
        st[(size_t)(o + 1) << 15] += 0.1f * (t1 + s1);
    }
}

// ---------------- channel mean ----------------

__global__ void k_final(float* __restrict__ out) {
    int b = blockIdx.y;
    int v = (blockIdx.x << 8) + threadIdx.x;
    const float* st = g_state + b * NC * VOL + v;
    float s = 0.f;
    #pragma unroll
    for (int c = 0; c < NC; c++) s += st[c << 15];
    out[b * VOL + v] = s * (1.f / 32.f);
}

// ---------------- launch ----------------

extern "C" void kernel_launch(void* const* d_in, const int* in_sizes, int n_in,
                              void* d_out, int out_size) {
    const float* z  = (const float*)d_in[0];
    const int*   y  = (const int*)d_in[1];
    const float* hw = (const float*)d_in[2];
    const float* hb = (const float*)d_in[3];
    float* out = (float*)d_out;
    (void)in_sizes; (void)n_in; (void)out_size;

    cudaFuncSetAttribute(k_residual, cudaFuncAttributeMaxDynamicSharedMemorySize,
                         SM_FLOATS * 4);

    k_norm<<<4, 256>>>(z);
    k_init<<<dim3(128, 4), 256>>>(z);
    k_theta<<<(BATCH * KT + 255) / 256, 256>>>(y, hw, hb);

    for (int it = 0; it < 4; it++) {
        k_sobel<<<dim3(32, 4), 512>>>();
        k_fold<<<4, 256>>>();
        k_residual<<<dim3(256, 4), 256, SM_FLOATS * 4>>>();
    }
    k_final<<<dim3(128, 4), 256>>>(out);
}